// round 1
// baseline (speedup 1.0000x reference)
#include <cuda_runtime.h>
#include <cuda_bf16.h>
#include <cstdint>

// Problem shape constants (fixed by the reference).
#define BB 2
#define LL 2048
#define DD 1024
#define HH 16
#define HD 64
#define ROWS (BB*LL)            // 4096
#define QKV_N (3*DD)            // 3072
#define BLD (BB*LL*DD)          // 4194304

// ---------------------------------------------------------------------------
// Scratch (alloc-free rule: __device__ globals)
// ---------------------------------------------------------------------------
__device__ float g_qkv[ROWS * QKV_N];     // [4096, 3072]
__device__ float g_q  [BLD];              // q heads (B,H,L,hd)
__device__ float g_ctx[BLD];              // attention context (B,L,D)

// ---------------------------------------------------------------------------
// NT SGEMM: C[m][n] = sum_k A[m][k]*B[n][k] + bias[n]
// A: [M,K] row-major, B: [N,K] row-major. M,N multiples of 128, K of 8.
// 256 threads, 128x128 block tile, 8x8 register tile.
// ---------------------------------------------------------------------------
__global__ __launch_bounds__(256) void sgemm_nt(
    const float* __restrict__ A, const float* __restrict__ B,
    const float* __restrict__ bias, float* __restrict__ C,
    int M, int N, int K)
{
    __shared__ float As[8][128];
    __shared__ float Bs[8][128];

    const int tid = threadIdx.x;
    const int tr  = tid >> 4;        // 0..15
    const int tc  = tid & 15;        // 0..15
    const int lr  = tid >> 1;        // 0..127 (load row)
    const int lc  = (tid & 1) * 4;   // 0 or 4 (load col within BK=8)

    const float* Ab = A + (size_t)(blockIdx.y * 128) * K;
    const float* Bb = B + (size_t)(blockIdx.x * 128) * K;

    float acc[8][8];
#pragma unroll
    for (int i = 0; i < 8; ++i)
#pragma unroll
        for (int j = 0; j < 8; ++j) acc[i][j] = 0.f;

    for (int k0 = 0; k0 < K; k0 += 8) {
        float4 a = *(const float4*)(Ab + (size_t)lr * K + k0 + lc);
        float4 b = *(const float4*)(Bb + (size_t)lr * K + k0 + lc);
        As[lc+0][lr] = a.x; As[lc+1][lr] = a.y; As[lc+2][lr] = a.z; As[lc+3][lr] = a.w;
        Bs[lc+0][lr] = b.x; Bs[lc+1][lr] = b.y; Bs[lc+2][lr] = b.z; Bs[lc+3][lr] = b.w;
        __syncthreads();

#pragma unroll
        for (int k = 0; k < 8; ++k) {
            float rm[8], rn[8];
            *(float4*)(rm)   = *(const float4*)&As[k][tr*8];
            *(float4*)(rm+4) = *(const float4*)&As[k][tr*8+4];
            *(float4*)(rn)   = *(const float4*)&Bs[k][tc*8];
            *(float4*)(rn+4) = *(const float4*)&Bs[k][tc*8+4];
#pragma unroll
            for (int i = 0; i < 8; ++i)
#pragma unroll
                for (int j = 0; j < 8; ++j)
                    acc[i][j] += rm[i] * rn[j];
        }
        __syncthreads();
    }

    const int row0 = blockIdx.y * 128 + tr * 8;
    const int col0 = blockIdx.x * 128 + tc * 8;
    float bb[8];
#pragma unroll
    for (int j = 0; j < 8; ++j) bb[j] = bias[col0 + j];
#pragma unroll
    for (int i = 0; i < 8; ++i) {
        float* Crow = C + (size_t)(row0 + i) * N + col0;
#pragma unroll
        for (int j = 0; j < 8; j += 4) {
            float4 o;
            o.x = acc[i][j+0] + bb[j+0];
            o.y = acc[i][j+1] + bb[j+1];
            o.z = acc[i][j+2] + bb[j+2];
            o.w = acc[i][j+3] + bb[j+3];
            *(float4*)(Crow + j) = o;
        }
    }
}

// ---------------------------------------------------------------------------
// RoPE + head scatter.
// qkv: [B*L, 3*D]. Writes q->g_q, k->kout, v->vout in (B,H,L,hd) layout.
// rotary_dim == hd == 64, half = 32. One thread per (b,l,h,d<32).
// ---------------------------------------------------------------------------
__global__ __launch_bounds__(256) void rope_scatter(
    const float* __restrict__ qkv, float* __restrict__ qh,
    float* __restrict__ kh, float* __restrict__ vh)
{
    const int t = blockIdx.x * blockDim.x + threadIdx.x;   // < 2^21
    const int d = t & 31;
    const int h = (t >> 5) & 15;
    const int l = (t >> 9) & 2047;
    const int b = t >> 20;

    const float* base = qkv + (size_t)(b * LL + l) * QKV_N;

    // inv_freq = 10000^(-d/32) = exp(-d * ln(10000)/32)
    const float inv = __expf(-(float)d * (9.210340371976184f / 32.f));
    const float ang = (float)l * inv;
    float sn, cs;
    sincosf(ang, &sn, &cs);

    const size_t ob = ((size_t)((b * HH + h) * LL + l)) * HD;

    const float q1 = base[h*HD + d],        q2 = base[h*HD + d + 32];
    qh[ob + d]      = q1 * cs - q2 * sn;
    qh[ob + d + 32] = q1 * sn + q2 * cs;

    const float k1 = base[DD + h*HD + d],   k2 = base[DD + h*HD + d + 32];
    kh[ob + d]      = k1 * cs - k2 * sn;
    kh[ob + d + 32] = k1 * sn + k2 * cs;

    vh[ob + d]      = base[2*DD + h*HD + d];
    vh[ob + d + 32] = base[2*DD + h*HD + d + 32];
}

// ---------------------------------------------------------------------------
// Flash attention, fp32, causal. Br=Bc=64, hd=64, 256 threads.
// Q,K,V in (B,H,L,hd); ctx written to (B,L,D).
// Shared: Qs[64][65], KPs[64][65] (K tile aliased with P tile), Vs[64][64],
//         red[64][17], stats (m,l,alpha,mnew)[64]  -> 55040 bytes dynamic.
// Thread (tr=tid/16, tc=tid%16) owns a 4x4 tile (rows tr*4.., cols tc*4..).
// ---------------------------------------------------------------------------
__global__ __launch_bounds__(256) void flash_kernel(
    const float* __restrict__ Q, const float* __restrict__ K,
    const float* __restrict__ V, float* __restrict__ ctx)
{
    extern __shared__ float sm[];
    float* Qs  = sm;                 // 64*65
    float* KPs = Qs  + 64*65;        // 64*65
    float* Vs  = KPs + 64*65;        // 64*64
    float* red = Vs  + 64*64;        // 64*17
    float* m_s = red + 64*17;        // 64
    float* l_s = m_s + 64;           // 64
    float* a_s = l_s + 64;           // 64
    float* n_s = a_s + 64;           // 64

    const int qi  = blockIdx.x;      // q tile index, 0..31
    const int bh  = blockIdx.y;      // 0..31
    const int tid = threadIdx.x;
    const int tr  = tid >> 4;        // 0..15
    const int tc  = tid & 15;        // 0..15

    const float* Qb = Q + ((size_t)bh * LL + qi * 64) * HD;
    const float* Kb = K + (size_t)bh * LL * HD;
    const float* Vb = V + (size_t)bh * LL * HD;

    // Load Q tile (pre-scaled by 1/sqrt(hd)=0.125), padded stride 65.
    {
        const int row = tid >> 4;          // 0..15 (+16*i)
        const int c4  = (tid & 15) * 4;
#pragma unroll
        for (int i = 0; i < 4; ++i) {
            const int r = row + i * 16;
            float4 v4 = *(const float4*)(Qb + (size_t)r * HD + c4);
            Qs[r*65 + c4 + 0] = v4.x * 0.125f;
            Qs[r*65 + c4 + 1] = v4.y * 0.125f;
            Qs[r*65 + c4 + 2] = v4.z * 0.125f;
            Qs[r*65 + c4 + 3] = v4.w * 0.125f;
        }
    }
    if (tid < 64) { m_s[tid] = -1e30f; l_s[tid] = 0.f; }

    float acc[4][4];
#pragma unroll
    for (int i = 0; i < 4; ++i)
#pragma unroll
        for (int j = 0; j < 4; ++j) acc[i][j] = 0.f;

    __syncthreads();

    for (int jt = 0; jt <= qi; ++jt) {
        // ---- load K (padded, stride 65) and V (linear) tiles ----
        {
            const float* Kt = Kb + (size_t)jt * 64 * HD;
            const float* Vt = Vb + (size_t)jt * 64 * HD;
            const int row = tid >> 4;
            const int c4  = (tid & 15) * 4;
#pragma unroll
            for (int i = 0; i < 4; ++i) {
                const int r = row + i * 16;
                float4 kv = *(const float4*)(Kt + (size_t)r * HD + c4);
                KPs[r*65 + c4 + 0] = kv.x;
                KPs[r*65 + c4 + 1] = kv.y;
                KPs[r*65 + c4 + 2] = kv.z;
                KPs[r*65 + c4 + 3] = kv.w;
                ((float4*)Vs)[tid + i * 256] = ((const float4*)Vt)[tid + i * 256];
            }
        }
        __syncthreads();

        // ---- S = Qs @ Ks^T (4x4 per thread) ----
        float s[4][4];
#pragma unroll
        for (int i = 0; i < 4; ++i)
#pragma unroll
            for (int j = 0; j < 4; ++j) s[i][j] = 0.f;

#pragma unroll 16
        for (int d = 0; d < 64; ++d) {
            float qv[4], kv[4];
#pragma unroll
            for (int i = 0; i < 4; ++i) qv[i] = Qs[(tr*4 + i) * 65 + d];
#pragma unroll
            for (int j = 0; j < 4; ++j) kv[j] = KPs[(tc*4 + j) * 65 + d];
#pragma unroll
            for (int i = 0; i < 4; ++i)
#pragma unroll
                for (int j = 0; j < 4; ++j)
                    s[i][j] += qv[i] * kv[j];
        }

        // ---- causal mask (matches reference's additive -1e9) ----
        if (jt == qi) {
            const int rg = qi * 64 + tr * 4;
            const int cg = jt * 64 + tc * 4;
#pragma unroll
            for (int i = 0; i < 4; ++i)
#pragma unroll
                for (int j = 0; j < 4; ++j)
                    if (cg + j > rg + i) s[i][j] += -1000000000.0f;
        }

        // ---- partial row max -> red ----
#pragma unroll
        for (int i = 0; i < 4; ++i) {
            float pm = fmaxf(fmaxf(s[i][0], s[i][1]), fmaxf(s[i][2], s[i][3]));
            red[(tr*4 + i) * 17 + tc] = pm;
        }
        __syncthreads();

        // ---- row max reduce, online-softmax stats ----
        if (tid < 64) {
            float mx = red[tid*17];
#pragma unroll
            for (int c = 1; c < 16; ++c) mx = fmaxf(mx, red[tid*17 + c]);
            const float mo = m_s[tid];
            const float mn = fmaxf(mo, mx);
            m_s[tid] = mn;
            n_s[tid] = mn;
            a_s[tid] = __expf(mo - mn);
        }
        __syncthreads();

        // ---- P = exp(S - m_new), write into KPs (K tile no longer needed),
        //      rescale accumulators, partial row sums -> red ----
#pragma unroll
        for (int i = 0; i < 4; ++i) {
            const int r = tr*4 + i;
            const float mn = n_s[r];
            const float al = a_s[r];
            float rs = 0.f;
#pragma unroll
            for (int j = 0; j < 4; ++j) {
                const float p = __expf(s[i][j] - mn);
                s[i][j] = p;
                rs += p;
                KPs[r*65 + tc*4 + j] = p;
            }
            red[r*17 + tc] = rs;
#pragma unroll
            for (int j = 0; j < 4; ++j) acc[i][j] *= al;
        }
        __syncthreads();

        // ---- l update ----
        if (tid < 64) {
            float sum = 0.f;
#pragma unroll
            for (int c = 0; c < 16; ++c) sum += red[tid*17 + c];
            l_s[tid] = l_s[tid] * a_s[tid] + sum;
        }

        // ---- O += P @ V ----
#pragma unroll 8
        for (int c = 0; c < 64; ++c) {
            float pv[4];
#pragma unroll
            for (int i = 0; i < 4; ++i) pv[i] = KPs[(tr*4 + i) * 65 + c];
            float4 vv = *(const float4*)(Vs + c * 64 + tc * 4);
#pragma unroll
            for (int i = 0; i < 4; ++i) {
                acc[i][0] += pv[i] * vv.x;
                acc[i][1] += pv[i] * vv.y;
                acc[i][2] += pv[i] * vv.z;
                acc[i][3] += pv[i] * vv.w;
            }
        }
        __syncthreads();   // protects KPs/Vs for next iter; publishes l_s
    }

    // ---- epilogue: O / l, write ctx in (B,L,D) ----
    const int b = bh >> 4;
    const int h = bh & 15;
#pragma unroll
    for (int i = 0; i < 4; ++i) {
        const int r = tr*4 + i;
        const float inv = 1.f / l_s[r];
        const int row_g = qi * 64 + r;
        float4 o;
        o.x = acc[i][0] * inv;
        o.y = acc[i][1] * inv;
        o.z = acc[i][2] * inv;
        o.w = acc[i][3] * inv;
        *(float4*)(ctx + ((size_t)(b * LL + row_g)) * DD + h * HD + tc * 4) = o;
    }
}

// ---------------------------------------------------------------------------
// Launch
// ---------------------------------------------------------------------------
extern "C" void kernel_launch(void* const* d_in, const int* in_sizes, int n_in,
                              void* d_out, int out_size)
{
    const float* x       = (const float*)d_in[0];
    // d_in[1] = mask (deterministic triu(-1e9,1); applied analytically)
    const float* Wqkv_w  = (const float*)d_in[2];
    const float* Wqkv_b  = (const float*)d_in[3];
    const float* Wout_w  = (const float*)d_in[4];
    const float* Wout_b  = (const float*)d_in[5];

    float* out  = (float*)d_out;          // (B,L,D)
    float* kout = out + BLD;              // (B,H,L,hd)
    float* vout = kout + BLD;             // (B,H,L,hd)

    float *qkv, *qh, *ctx;
    cudaGetSymbolAddress((void**)&qkv, g_qkv);
    cudaGetSymbolAddress((void**)&qh,  g_q);
    cudaGetSymbolAddress((void**)&ctx, g_ctx);

    // 1) QKV projection: [4096,1024] x [3072,1024]^T
    sgemm_nt<<<dim3(QKV_N/128, ROWS/128), 256>>>(x, Wqkv_w, Wqkv_b, qkv,
                                                 ROWS, QKV_N, DD);

    // 2) RoPE + head scatter (k, v land directly in d_out)
    rope_scatter<<<(BB*LL*HH*32)/256, 256>>>(qkv, qh, kout, vout);

    // 3) Causal flash attention
    const int flash_smem = (64*65 + 64*65 + 64*64 + 64*17 + 4*64) * 4;
    cudaFuncSetAttribute(flash_kernel,
                         cudaFuncAttributeMaxDynamicSharedMemorySize, flash_smem);
    flash_kernel<<<dim3(LL/64, BB*HH), 256, flash_smem>>>(qh, kout, vout, ctx);

    // 4) Output projection: [4096,1024] x [1024,1024]^T
    sgemm_nt<<<dim3(DD/128, ROWS/128), 256>>>(ctx, Wout_w, Wout_b, out,
                                              ROWS, DD, DD);
}

// round 3
// speedup vs baseline: 2.7182x; 2.7182x over previous
#include <cuda_runtime.h>
#include <cuda_bf16.h>
#include <cstdint>

// Problem shape constants (fixed by the reference).
#define BB 2
#define LL 2048
#define DD 1024
#define HH 16
#define HD 64
#define ROWS (BB*LL)            // 4096
#define QKV_N (3*DD)            // 3072
#define BLD (BB*LL*DD)          // 4194304

// ---------------------------------------------------------------------------
// Scratch (alloc-free rule: __device__ globals)
// ---------------------------------------------------------------------------
__device__ float g_xr  [BLD];             // x rounded to tf32
__device__ float g_wqkv[QKV_N * DD];      // Wqkv rounded
__device__ float g_wout[DD * DD];         // Wout rounded
__device__ float g_qkv [ROWS * QKV_N];    // qkv projection (fp32)
__device__ float g_q   [BLD];             // q heads, rope'd, scaled, rounded
__device__ float g_k   [BLD];             // k heads, rope'd, rounded
__device__ float g_v   [BLD];             // v heads, rounded
__device__ float g_ctx [BLD];             // attention context, rounded

// ---------------------------------------------------------------------------
// Helpers
// ---------------------------------------------------------------------------
__device__ __forceinline__ uint32_t f2tf(float f) {
    uint32_t r;
    asm("cvt.rna.tf32.f32 %0, %1;" : "=r"(r) : "f"(f));
    return r;
}

__device__ __forceinline__ uint32_t smem_u32(const void* p) {
    uint32_t a;
    asm("{ .reg .u64 t; cvta.to.shared.u64 t, %1; cvt.u32.u64 %0, t; }"
        : "=r"(a) : "l"(p));
    return a;
}

// m16n8k8 tf32 mma: C += A * B^T-ish (.row.col)
__device__ __forceinline__ void mma8(float* c, const uint32_t* a, const uint32_t* b) {
    asm volatile(
        "mma.sync.aligned.m16n8k8.row.col.f32.tf32.tf32.f32 "
        "{%0,%1,%2,%3}, {%4,%5,%6,%7}, {%8,%9}, {%0,%1,%2,%3};"
        : "+f"(c[0]), "+f"(c[1]), "+f"(c[2]), "+f"(c[3])
        : "r"(a[0]), "r"(a[1]), "r"(a[2]), "r"(a[3]), "r"(b[0]), "r"(b[1]));
}

#define CP16(dst, src) \
    asm volatile("cp.async.cg.shared.global [%0], [%1], 16;" :: "r"(dst), "l"(src))
#define CP_COMMIT() asm volatile("cp.async.commit_group;" ::: "memory")
#define CP_WAIT(n)  asm volatile("cp.async.wait_group %0;" :: "n"(n) : "memory")

// ---------------------------------------------------------------------------
// Elementwise round-to-tf32 (RNA)
// ---------------------------------------------------------------------------
__global__ __launch_bounds__(256) void round_tf32(
    const float* __restrict__ in, float* __restrict__ out, int n)
{
    int i = blockIdx.x * 256 + threadIdx.x;
    if (i < n) out[i] = __uint_as_float(f2tf(in[i]));
}

// ---------------------------------------------------------------------------
// tf32 mma.sync NT GEMM: C[m][n] = sum_k A[m][k]*B[n][k] + bias[n]
// 128x128 CTA tile, BK=32, 128 threads (4 warps, 2x2 of 64x64 warp tiles).
// Inputs must be pre-rounded to tf32. smem pad stride 36 (conflict-free).
// ---------------------------------------------------------------------------
#define GSTR 36
#define GEMM_SMEM (2 * 2 * 128 * GSTR * 4)   // A[2] + B[2] buffers

__global__ __launch_bounds__(128) void gemm_mma(
    const float* __restrict__ A, const float* __restrict__ B,
    const float* __restrict__ bias, float* __restrict__ C,
    int N, int K)
{
    extern __shared__ float sm[];
    float* As = sm;                      // [2][128*GSTR]
    float* Bs = sm + 2 * 128 * GSTR;
    const uint32_t As_u = smem_u32(As);
    const uint32_t Bs_u = smem_u32(Bs);

    const int tid  = threadIdx.x;
    const int lane = tid & 31;
    const int wid  = tid >> 5;
    const int wm   = wid & 1;            // warp row (2 x 64)
    const int wn   = wid >> 1;           // warp col (2 x 64)
    const int lq   = lane >> 2;          // 0..7
    const int ls   = lane & 3;           // 0..3

    const float* Ab = A + (size_t)(blockIdx.y * 128) * K;
    const float* Bb = B + (size_t)(blockIdx.x * 128) * K;
    const int KS = K >> 5;

    float acc[4][8][4];
#pragma unroll
    for (int mt = 0; mt < 4; ++mt)
#pragma unroll
        for (int nt = 0; nt < 8; ++nt)
#pragma unroll
            for (int r = 0; r < 4; ++r) acc[mt][nt][r] = 0.f;

    // tile loader: 8 16B chunks per matrix per thread
#define GEMM_LOAD(ks, db)                                                     \
    {                                                                         \
        const int k0 = (ks) * 32;                                             \
        const uint32_t dA = As_u + (db) * 128 * GSTR * 4;                     \
        const uint32_t dB = Bs_u + (db) * 128 * GSTR * 4;                     \
        _Pragma("unroll")                                                     \
        for (int i = 0; i < 8; ++i) {                                         \
            const int c   = tid + i * 128;                                    \
            const int row = c >> 3;                                           \
            const int cc  = (c & 7) * 4;                                      \
            const uint32_t off = (uint32_t)(row * GSTR + cc) * 4;             \
            CP16(dA + off, Ab + (size_t)row * K + k0 + cc);                   \
            CP16(dB + off, Bb + (size_t)row * K + k0 + cc);                   \
        }                                                                     \
        CP_COMMIT();                                                          \
    }

    GEMM_LOAD(0, 0);

    for (int ks = 0; ks < KS; ++ks) {
        const int db = ks & 1;
        if (ks + 1 < KS) { GEMM_LOAD(ks + 1, db ^ 1); CP_WAIT(1); }
        else             { CP_WAIT(0); }
        __syncthreads();

        const float* Ad = As + db * 128 * GSTR;
        const float* Bd = Bs + db * 128 * GSTR;

#pragma unroll
        for (int kb = 0; kb < 4; ++kb) {
            const int k = kb * 8 + ls;
            uint32_t a[4][4], b[8][2];
#pragma unroll
            for (int mt = 0; mt < 4; ++mt) {
                const int r = wm * 64 + mt * 16 + lq;
                a[mt][0] = __float_as_uint(Ad[r * GSTR + k]);
                a[mt][1] = __float_as_uint(Ad[(r + 8) * GSTR + k]);
                a[mt][2] = __float_as_uint(Ad[r * GSTR + k + 4]);
                a[mt][3] = __float_as_uint(Ad[(r + 8) * GSTR + k + 4]);
            }
#pragma unroll
            for (int nt = 0; nt < 8; ++nt) {
                const int cn = wn * 64 + nt * 8 + lq;
                b[nt][0] = __float_as_uint(Bd[cn * GSTR + k]);
                b[nt][1] = __float_as_uint(Bd[cn * GSTR + k + 4]);
            }
#pragma unroll
            for (int mt = 0; mt < 4; ++mt)
#pragma unroll
                for (int nt = 0; nt < 8; ++nt)
                    mma8(acc[mt][nt], a[mt], b[nt]);
        }
        __syncthreads();
    }

    // epilogue
    const int row_base = blockIdx.y * 128 + wm * 64;
    const int col_base = blockIdx.x * 128 + wn * 64;
#pragma unroll
    for (int mt = 0; mt < 4; ++mt) {
        const int r0 = row_base + mt * 16 + lq;
#pragma unroll
        for (int nt = 0; nt < 8; ++nt) {
            const int cn = col_base + nt * 8 + ls * 2;
            const float2 bb = *(const float2*)(bias + cn);
            float2 o0, o1;
            o0.x = acc[mt][nt][0] + bb.x;  o0.y = acc[mt][nt][1] + bb.y;
            o1.x = acc[mt][nt][2] + bb.x;  o1.y = acc[mt][nt][3] + bb.y;
            *(float2*)(C + (size_t)r0 * N + cn)       = o0;
            *(float2*)(C + (size_t)(r0 + 8) * N + cn) = o1;
        }
    }
}

// ---------------------------------------------------------------------------
// RoPE + head scatter. Exact k,v -> d_out; rounded q(scaled)/k/v -> flash bufs.
// ---------------------------------------------------------------------------
__global__ __launch_bounds__(256) void rope_scatter(
    const float* __restrict__ qkv,
    float* __restrict__ qh, float* __restrict__ kh, float* __restrict__ vh,
    float* __restrict__ kout, float* __restrict__ vout)
{
    const int t = blockIdx.x * blockDim.x + threadIdx.x;
    const int d = t & 31;
    const int h = (t >> 5) & 15;
    const int l = (t >> 9) & 2047;
    const int b = t >> 20;

    const float* base = qkv + (size_t)(b * LL + l) * QKV_N;

    const float inv = __expf(-(float)d * (9.210340371976184f / 32.f));
    const float ang = (float)l * inv;
    float sn, cs;
    sincosf(ang, &sn, &cs);

    const size_t ob = ((size_t)((b * HH + h) * LL + l)) * HD;

    const float q1 = base[h*HD + d], q2 = base[h*HD + d + 32];
    qh[ob + d]      = __uint_as_float(f2tf((q1 * cs - q2 * sn) * 0.125f));
    qh[ob + d + 32] = __uint_as_float(f2tf((q1 * sn + q2 * cs) * 0.125f));

    const float k1 = base[DD + h*HD + d], k2 = base[DD + h*HD + d + 32];
    const float kr1 = k1 * cs - k2 * sn;
    const float kr2 = k1 * sn + k2 * cs;
    kout[ob + d]      = kr1;
    kout[ob + d + 32] = kr2;
    kh[ob + d]        = __uint_as_float(f2tf(kr1));
    kh[ob + d + 32]   = __uint_as_float(f2tf(kr2));

    const float v1 = base[2*DD + h*HD + d], v2 = base[2*DD + h*HD + d + 32];
    vout[ob + d]      = v1;
    vout[ob + d + 32] = v2;
    vh[ob + d]        = __uint_as_float(f2tf(v1));
    vh[ob + d + 32]   = __uint_as_float(f2tf(v2));
}

// ---------------------------------------------------------------------------
// Flash attention, tf32 mma.sync, causal. Br=Bc=64, 128 threads (4 warps).
// Warp w owns rows [w*16, w*16+16). All smem tiles stride 68 (conflict-free).
// smem: Qs | Ks[2] | Vt[2] (V transposed: [dim][token]) | Ps  = 6*64*68 floats.
// ---------------------------------------------------------------------------
#define FSTR 68
#define FLASH_SMEM (6 * 64 * FSTR * 4)

__global__ __launch_bounds__(128) void flash_mma(
    const float* __restrict__ Q, const float* __restrict__ K,
    const float* __restrict__ V, float* __restrict__ ctx)
{
    extern __shared__ float sm[];
    float* Qs = sm;                      // 64*FSTR
    float* Ks = Qs + 64 * FSTR;          // [2][64*FSTR]
    float* Vt = Ks + 2 * 64 * FSTR;      // [2][64*FSTR]  (transposed V)
    float* Ps = Vt + 2 * 64 * FSTR;      // 64*FSTR
    const uint32_t Qs_u = smem_u32(Qs);
    const uint32_t Ks_u = smem_u32(Ks);

    const int qi   = blockIdx.x;         // q tile 0..31
    const int bh   = blockIdx.y;         // 0..31
    const int tid  = threadIdx.x;
    const int lane = tid & 31;
    const int wid  = tid >> 5;
    const int lq   = lane >> 2;          // 0..7
    const int ls   = lane & 3;           // 0..3

    const float* Qb = Q + ((size_t)bh * LL + qi * 64) * HD;
    const float* Kb = K + (size_t)bh * LL * HD;
    const float* Vb = V + (size_t)bh * LL * HD;

    // cp.async loaders for Q / K tiles: 64x64 floats, row stride FSTR.
#define FL_LOAD(dst_u, src)                                                   \
    {                                                                         \
        _Pragma("unroll")                                                     \
        for (int i = 0; i < 8; ++i) {                                         \
            const int c   = tid + i * 128;                                    \
            const int row = c >> 4;                                           \
            const int cc  = (c & 15) * 4;                                     \
            CP16((dst_u) + (uint32_t)(row * FSTR + cc) * 4,                   \
                 (src) + (size_t)row * HD + cc);                              \
        }                                                                     \
    }

    const int vtok  = tid & 63;          // V loader: one token per thread
    const int vhalf = tid >> 6;          // which 32 dims

    float4 vr[8];
#define FL_LDG_V(jt)                                                          \
    {                                                                         \
        const float* vb = Vb + ((size_t)(jt) * 64 + vtok) * HD + vhalf * 32;  \
        _Pragma("unroll")                                                     \
        for (int i = 0; i < 8; ++i) vr[i] = *(const float4*)(vb + i * 4);     \
    }

#define FL_STS_V(db)                                                          \
    {                                                                         \
        float* vt = Vt + (db) * 64 * FSTR;                                    \
        _Pragma("unroll")                                                     \
        for (int i = 0; i < 8; ++i) {                                         \
            const int c0 = vhalf * 32 + i * 4;                                \
            vt[(c0 + 0) * FSTR + vtok] = vr[i].x;                             \
            vt[(c0 + 1) * FSTR + vtok] = vr[i].y;                             \
            vt[(c0 + 2) * FSTR + vtok] = vr[i].z;                             \
            vt[(c0 + 3) * FSTR + vtok] = vr[i].w;                             \
        }                                                                     \
    }

    // prologue: Q + K0 in one cp.async group, V0 into regs
    FL_LOAD(Qs_u, Qb);
    FL_LOAD(Ks_u, Kb);
    CP_COMMIT();
    FL_LDG_V(0);

    float acc[8][4];
#pragma unroll
    for (int nt = 0; nt < 8; ++nt)
#pragma unroll
        for (int r = 0; r < 4; ++r) acc[nt][r] = 0.f;
    float m0 = -1e30f, m1 = -1e30f, l0 = 0.f, l1 = 0.f;

    const int rrow = wid * 16 + lq;      // this thread's row pair: rrow, rrow+8

    for (int jt = 0; jt <= qi; ++jt) {
        const int db = jt & 1;
        CP_WAIT(0);                      // K_jt (and Q on jt=0) in smem
        FL_STS_V(db);
        __syncthreads();

        if (jt < qi) {                   // prefetch next K + V
            FL_LOAD(Ks_u + (uint32_t)((db ^ 1) * 64 * FSTR) * 4,
                    Kb + (size_t)(jt + 1) * 64 * HD);
            CP_COMMIT();
            FL_LDG_V(jt + 1);
        }

        // ---- S = Q K^T ----
        float sc[8][4];
#pragma unroll
        for (int nt = 0; nt < 8; ++nt)
#pragma unroll
            for (int r = 0; r < 4; ++r) sc[nt][r] = 0.f;

        const float* Kd = Ks + db * 64 * FSTR;
#pragma unroll
        for (int kb = 0; kb < 8; ++kb) {
            const int k = kb * 8 + ls;
            uint32_t a[4];
            a[0] = __float_as_uint(Qs[rrow * FSTR + k]);
            a[1] = __float_as_uint(Qs[(rrow + 8) * FSTR + k]);
            a[2] = __float_as_uint(Qs[rrow * FSTR + k + 4]);
            a[3] = __float_as_uint(Qs[(rrow + 8) * FSTR + k + 4]);
#pragma unroll
            for (int nt = 0; nt < 8; ++nt) {
                uint32_t b[2];
                const int cn = nt * 8 + lq;
                b[0] = __float_as_uint(Kd[cn * FSTR + k]);
                b[1] = __float_as_uint(Kd[cn * FSTR + k + 4]);
                mma8(sc[nt], a, b);
            }
        }

        // ---- causal mask on diagonal tile ----
        if (jt == qi) {
            const int rg0 = qi * 64 + rrow;
#pragma unroll
            for (int nt = 0; nt < 8; ++nt) {
                const int cg = jt * 64 + nt * 8 + ls * 2;
                if (cg > rg0)         sc[nt][0] += -1000000000.0f;
                if (cg + 1 > rg0)     sc[nt][1] += -1000000000.0f;
                if (cg > rg0 + 8)     sc[nt][2] += -1000000000.0f;
                if (cg + 1 > rg0 + 8) sc[nt][3] += -1000000000.0f;
            }
        }

        // ---- row max (thread-local + quad shfl) ----
        float mx0 = sc[0][0], mx1 = sc[0][2];
#pragma unroll
        for (int nt = 0; nt < 8; ++nt) {
            mx0 = fmaxf(mx0, fmaxf(sc[nt][0], sc[nt][1]));
            mx1 = fmaxf(mx1, fmaxf(sc[nt][2], sc[nt][3]));
        }
        mx0 = fmaxf(mx0, __shfl_xor_sync(0xffffffffu, mx0, 1));
        mx0 = fmaxf(mx0, __shfl_xor_sync(0xffffffffu, mx0, 2));
        mx1 = fmaxf(mx1, __shfl_xor_sync(0xffffffffu, mx1, 1));
        mx1 = fmaxf(mx1, __shfl_xor_sync(0xffffffffu, mx1, 2));

        const float mn0 = fmaxf(m0, mx0);
        const float mn1 = fmaxf(m1, mx1);
        const float al0 = __expf(m0 - mn0);
        const float al1 = __expf(m1 - mn1);
        m0 = mn0; m1 = mn1;

        // ---- P = exp(S - m), round, store to Ps; row sums ----
        float rs0 = 0.f, rs1 = 0.f;
#pragma unroll
        for (int nt = 0; nt < 8; ++nt) {
            const float p0 = __expf(sc[nt][0] - mn0);
            const float p1 = __expf(sc[nt][1] - mn0);
            const float p2 = __expf(sc[nt][2] - mn1);
            const float p3 = __expf(sc[nt][3] - mn1);
            rs0 += p0 + p1;  rs1 += p2 + p3;
            uint2 w0, w1;
            w0.x = f2tf(p0); w0.y = f2tf(p1);
            w1.x = f2tf(p2); w1.y = f2tf(p3);
            const int cc = nt * 8 + ls * 2;
            *(uint2*)(Ps + rrow * FSTR + cc)       = w0;
            *(uint2*)(Ps + (rrow + 8) * FSTR + cc) = w1;
        }
        rs0 += __shfl_xor_sync(0xffffffffu, rs0, 1);
        rs0 += __shfl_xor_sync(0xffffffffu, rs0, 2);
        rs1 += __shfl_xor_sync(0xffffffffu, rs1, 1);
        rs1 += __shfl_xor_sync(0xffffffffu, rs1, 2);
        l0 = l0 * al0 + rs0;
        l1 = l1 * al1 + rs1;

        // ---- rescale accumulators ----
#pragma unroll
        for (int nt = 0; nt < 8; ++nt) {
            acc[nt][0] *= al0; acc[nt][1] *= al0;
            acc[nt][2] *= al1; acc[nt][3] *= al1;
        }
        __syncwarp();

        // ---- O += P V ----
        const float* Vd = Vt + db * 64 * FSTR;
#pragma unroll
        for (int kb = 0; kb < 8; ++kb) {
            const int k = kb * 8 + ls;
            uint32_t a[4];
            a[0] = __float_as_uint(Ps[rrow * FSTR + k]);
            a[1] = __float_as_uint(Ps[(rrow + 8) * FSTR + k]);
            a[2] = __float_as_uint(Ps[rrow * FSTR + k + 4]);
            a[3] = __float_as_uint(Ps[(rrow + 8) * FSTR + k + 4]);
#pragma unroll
            for (int nt = 0; nt < 8; ++nt) {
                uint32_t b[2];
                const int cn = nt * 8 + lq;
                b[0] = __float_as_uint(Vd[cn * FSTR + k]);
                b[1] = __float_as_uint(Vd[cn * FSTR + k + 4]);
                mma8(acc[nt], a, b);
            }
        }
        __syncthreads();
    }

    // ---- epilogue: O / l, round to tf32, write ctx (B,L,D) ----
    const float inv0 = 1.f / l0;
    const float inv1 = 1.f / l1;
    const int b = bh >> 4;
    const int h = bh & 15;
    const int r0 = qi * 64 + rrow;
#pragma unroll
    for (int nt = 0; nt < 8; ++nt) {
        const int cn = h * HD + nt * 8 + ls * 2;
        uint2 o0, o1;
        o0.x = f2tf(acc[nt][0] * inv0); o0.y = f2tf(acc[nt][1] * inv0);
        o1.x = f2tf(acc[nt][2] * inv1); o1.y = f2tf(acc[nt][3] * inv1);
        *(uint2*)(ctx + (size_t)(b * LL + r0) * DD + cn)     = o0;
        *(uint2*)(ctx + (size_t)(b * LL + r0 + 8) * DD + cn) = o1;
    }
}

// ---------------------------------------------------------------------------
// Launch
// ---------------------------------------------------------------------------
extern "C" void kernel_launch(void* const* d_in, const int* in_sizes, int n_in,
                              void* d_out, int out_size)
{
    const float* x       = (const float*)d_in[0];
    // d_in[1] = mask (deterministic triu(-1e9,1); applied analytically)
    const float* Wqkv_w  = (const float*)d_in[2];
    const float* Wqkv_b  = (const float*)d_in[3];
    const float* Wout_w  = (const float*)d_in[4];
    const float* Wout_b  = (const float*)d_in[5];

    float* out  = (float*)d_out;          // (B,L,D)
    float* kout = out + BLD;              // (B,H,L,hd)
    float* vout = kout + BLD;             // (B,H,L,hd)

    float *xr, *wqkv, *wout_r, *qkv, *qh, *kh, *vh, *ctx;
    cudaGetSymbolAddress((void**)&xr,     g_xr);
    cudaGetSymbolAddress((void**)&wqkv,   g_wqkv);
    cudaGetSymbolAddress((void**)&wout_r, g_wout);
    cudaGetSymbolAddress((void**)&qkv,    g_qkv);
    cudaGetSymbolAddress((void**)&qh,     g_q);
    cudaGetSymbolAddress((void**)&kh,     g_k);
    cudaGetSymbolAddress((void**)&vh,     g_v);
    cudaGetSymbolAddress((void**)&ctx,    g_ctx);

    cudaFuncSetAttribute(gemm_mma,
                         cudaFuncAttributeMaxDynamicSharedMemorySize, GEMM_SMEM);
    cudaFuncSetAttribute(flash_mma,
                         cudaFuncAttributeMaxDynamicSharedMemorySize, FLASH_SMEM);

    // 0) round inputs to tf32 (RNA)
    round_tf32<<<(BLD + 255) / 256, 256>>>(x, xr, BLD);
    round_tf32<<<(QKV_N * DD + 255) / 256, 256>>>(Wqkv_w, wqkv, QKV_N * DD);
    round_tf32<<<(DD * DD + 255) / 256, 256>>>(Wout_w, wout_r, DD * DD);

    // 1) QKV projection: [4096,1024] x [3072,1024]^T
    gemm_mma<<<dim3(QKV_N / 128, ROWS / 128), 128, GEMM_SMEM>>>(
        xr, wqkv, Wqkv_b, qkv, QKV_N, DD);

    // 2) RoPE + head scatter (exact k,v -> d_out; rounded copies for flash)
    rope_scatter<<<(BB * LL * HH * 32) / 256, 256>>>(qkv, qh, kh, vh, kout, vout);

    // 3) Causal flash attention (tf32 mma)
    flash_mma<<<dim3(LL / 64, BB * HH), 128, FLASH_SMEM>>>(qh, kh, vh, ctx);

    // 4) Output projection: [4096,1024] x [1024,1024]^T
    gemm_mma<<<dim3(DD / 128, ROWS / 128), 128, GEMM_SMEM>>>(
        ctx, wout_r, Wout_b, out, DD, DD);
}

// round 4
// speedup vs baseline: 2.8526x; 1.0495x over previous
#include <cuda_runtime.h>
#include <cuda_bf16.h>
#include <cstdint>

// Problem shape constants (fixed by the reference).
#define BB 2
#define LL 2048
#define DD 1024
#define HH 16
#define HD 64
#define ROWS (BB*LL)            // 4096
#define QKV_N (3*DD)            // 3072
#define BLD (BB*LL*DD)          // 4194304
#define WQKV_SZ (QKV_N*DD)      // 3145728
#define WOUT_SZ (DD*DD)         // 1048576

// ---------------------------------------------------------------------------
// Scratch (alloc-free rule: __device__ globals)
// ---------------------------------------------------------------------------
__device__ float g_xr  [BLD];             // x rounded to tf32
__device__ float g_wqkv[WQKV_SZ];         // Wqkv rounded
__device__ float g_wout[WOUT_SZ];         // Wout rounded
__device__ float g_qkv [ROWS * QKV_N];    // qkv projection (fp32)
__device__ float g_q   [BLD];             // q heads, rope'd, scaled, rounded
__device__ float g_k   [BLD];             // k heads, rope'd, rounded
__device__ float g_v   [BLD];             // v heads, rounded
__device__ float g_ctx [BLD];             // attention context, rounded

// ---------------------------------------------------------------------------
// Helpers
// ---------------------------------------------------------------------------
__device__ __forceinline__ uint32_t f2tf(float f) {
    uint32_t r;
    asm("cvt.rna.tf32.f32 %0, %1;" : "=r"(r) : "f"(f));
    return r;
}

__device__ __forceinline__ uint32_t smem_u32(const void* p) {
    uint32_t a;
    asm("{ .reg .u64 t; cvta.to.shared.u64 t, %1; cvt.u32.u64 %0, t; }"
        : "=r"(a) : "l"(p));
    return a;
}

// m16n8k8 tf32 mma (.row.col)
__device__ __forceinline__ void mma8(float* c, const uint32_t* a, const uint32_t* b) {
    asm volatile(
        "mma.sync.aligned.m16n8k8.row.col.f32.tf32.tf32.f32 "
        "{%0,%1,%2,%3}, {%4,%5,%6,%7}, {%8,%9}, {%0,%1,%2,%3};"
        : "+f"(c[0]), "+f"(c[1]), "+f"(c[2]), "+f"(c[3])
        : "r"(a[0]), "r"(a[1]), "r"(a[2]), "r"(a[3]), "r"(b[0]), "r"(b[1]));
}

#define CP16(dst, src) \
    asm volatile("cp.async.cg.shared.global [%0], [%1], 16;" :: "r"(dst), "l"(src))
#define CP_COMMIT() asm volatile("cp.async.commit_group;" ::: "memory")
#define CP_WAIT(n)  asm volatile("cp.async.wait_group %0;" :: "n"(n) : "memory")

// ---------------------------------------------------------------------------
// Fused round-to-tf32 of x, Wqkv, Wout (one launch, float4 grid-stride)
// ---------------------------------------------------------------------------
#define RND_TOTAL4 ((BLD + WQKV_SZ + WOUT_SZ) / 4)

__global__ __launch_bounds__(256) void round_all(
    const float4* __restrict__ x,   float4* __restrict__ xr,
    const float4* __restrict__ wq,  float4* __restrict__ wqr,
    const float4* __restrict__ wo,  float4* __restrict__ wor)
{
    int i = blockIdx.x * 256 + threadIdx.x;
    if (i >= RND_TOTAL4) return;
    const float4* src; float4* dst;
    if (i < BLD/4)                       { src = x;  dst = xr;  }
    else if (i < (BLD + WQKV_SZ)/4)      { src = wq; dst = wqr; i -= BLD/4; }
    else                                 { src = wo; dst = wor; i -= (BLD + WQKV_SZ)/4; }
    float4 v = src[i];
    float4 o;
    o.x = __uint_as_float(f2tf(v.x));
    o.y = __uint_as_float(f2tf(v.y));
    o.z = __uint_as_float(f2tf(v.z));
    o.w = __uint_as_float(f2tf(v.w));
    dst[i] = o;
}

// ---------------------------------------------------------------------------
// tf32 mma.sync NT GEMM: C[m][n] = sum_k A[m][k]*B[n][k] + bias[n]
// 128x128 CTA tile, BK=32, 256 threads (8 warps, 2x4 grid of 64x32 warp tiles).
// Inputs must be pre-rounded to tf32. smem pad stride 36 (conflict-free).
// ---------------------------------------------------------------------------
#define GSTR 36
#define GEMM_SMEM (2 * 2 * 128 * GSTR * 4)   // A[2] + B[2] buffers

__global__ __launch_bounds__(256) void gemm_mma(
    const float* __restrict__ A, const float* __restrict__ B,
    const float* __restrict__ bias, float* __restrict__ C,
    int N, int K)
{
    extern __shared__ float sm[];
    float* As = sm;                      // [2][128*GSTR]
    float* Bs = sm + 2 * 128 * GSTR;
    const uint32_t As_u = smem_u32(As);
    const uint32_t Bs_u = smem_u32(Bs);

    const int tid  = threadIdx.x;
    const int lane = tid & 31;
    const int wid  = tid >> 5;
    const int wm   = wid & 1;            // warp row (2 x 64 rows)
    const int wn   = wid >> 1;           // warp col (4 x 32 cols)
    const int lq   = lane >> 2;          // 0..7
    const int ls   = lane & 3;           // 0..3

    const float* Ab = A + (size_t)(blockIdx.y * 128) * K;
    const float* Bb = B + (size_t)(blockIdx.x * 128) * K;
    const int KS = K >> 5;

    float acc[4][4][4];
#pragma unroll
    for (int mt = 0; mt < 4; ++mt)
#pragma unroll
        for (int nt = 0; nt < 4; ++nt)
#pragma unroll
            for (int r = 0; r < 4; ++r) acc[mt][nt][r] = 0.f;

    // tile loader: 4 16B chunks per matrix per thread (256 thr)
#define GEMM_LOAD(ks, db)                                                     \
    {                                                                         \
        const int k0 = (ks) * 32;                                             \
        const uint32_t dA = As_u + (db) * 128 * GSTR * 4;                     \
        const uint32_t dB = Bs_u + (db) * 128 * GSTR * 4;                     \
        _Pragma("unroll")                                                     \
        for (int i = 0; i < 4; ++i) {                                         \
            const int c   = tid + i * 256;                                    \
            const int row = c >> 3;                                           \
            const int cc  = (c & 7) * 4;                                      \
            const uint32_t off = (uint32_t)(row * GSTR + cc) * 4;             \
            CP16(dA + off, Ab + (size_t)row * K + k0 + cc);                   \
            CP16(dB + off, Bb + (size_t)row * K + k0 + cc);                   \
        }                                                                     \
        CP_COMMIT();                                                          \
    }

    GEMM_LOAD(0, 0);

    for (int ks = 0; ks < KS; ++ks) {
        const int db = ks & 1;
        if (ks + 1 < KS) { GEMM_LOAD(ks + 1, db ^ 1); CP_WAIT(1); }
        else             { CP_WAIT(0); }
        __syncthreads();

        const float* Ad = As + db * 128 * GSTR;
        const float* Bd = Bs + db * 128 * GSTR;

#pragma unroll
        for (int kb = 0; kb < 4; ++kb) {
            const int k = kb * 8 + ls;
            uint32_t a[4][4], b[4][2];
#pragma unroll
            for (int mt = 0; mt < 4; ++mt) {
                const int r = wm * 64 + mt * 16 + lq;
                a[mt][0] = __float_as_uint(Ad[r * GSTR + k]);
                a[mt][1] = __float_as_uint(Ad[(r + 8) * GSTR + k]);
                a[mt][2] = __float_as_uint(Ad[r * GSTR + k + 4]);
                a[mt][3] = __float_as_uint(Ad[(r + 8) * GSTR + k + 4]);
            }
#pragma unroll
            for (int nt = 0; nt < 4; ++nt) {
                const int cn = wn * 32 + nt * 8 + lq;
                b[nt][0] = __float_as_uint(Bd[cn * GSTR + k]);
                b[nt][1] = __float_as_uint(Bd[cn * GSTR + k + 4]);
            }
#pragma unroll
            for (int mt = 0; mt < 4; ++mt)
#pragma unroll
                for (int nt = 0; nt < 4; ++nt)
                    mma8(acc[mt][nt], a[mt], b[nt]);
        }
        __syncthreads();
    }

    // epilogue
    const int row_base = blockIdx.y * 128 + wm * 64;
    const int col_base = blockIdx.x * 128 + wn * 32;
#pragma unroll
    for (int mt = 0; mt < 4; ++mt) {
        const int r0 = row_base + mt * 16 + lq;
#pragma unroll
        for (int nt = 0; nt < 4; ++nt) {
            const int cn = col_base + nt * 8 + ls * 2;
            const float2 bb = *(const float2*)(bias + cn);
            float2 o0, o1;
            o0.x = acc[mt][nt][0] + bb.x;  o0.y = acc[mt][nt][1] + bb.y;
            o1.x = acc[mt][nt][2] + bb.x;  o1.y = acc[mt][nt][3] + bb.y;
            *(float2*)(C + (size_t)r0 * N + cn)       = o0;
            *(float2*)(C + (size_t)(r0 + 8) * N + cn) = o1;
        }
    }
}

// ---------------------------------------------------------------------------
// RoPE + head scatter. Exact k,v -> d_out; rounded q(scaled)/k/v -> flash bufs.
// ---------------------------------------------------------------------------
__global__ __launch_bounds__(256) void rope_scatter(
    const float* __restrict__ qkv,
    float* __restrict__ qh, float* __restrict__ kh, float* __restrict__ vh,
    float* __restrict__ kout, float* __restrict__ vout)
{
    const int t = blockIdx.x * blockDim.x + threadIdx.x;
    const int d = t & 31;
    const int h = (t >> 5) & 15;
    const int l = (t >> 9) & 2047;
    const int b = t >> 20;

    const float* base = qkv + (size_t)(b * LL + l) * QKV_N;

    const float inv = __expf(-(float)d * (9.210340371976184f / 32.f));
    const float ang = (float)l * inv;
    float sn, cs;
    sincosf(ang, &sn, &cs);

    const size_t ob = ((size_t)((b * HH + h) * LL + l)) * HD;

    const float q1 = base[h*HD + d], q2 = base[h*HD + d + 32];
    qh[ob + d]      = __uint_as_float(f2tf((q1 * cs - q2 * sn) * 0.125f));
    qh[ob + d + 32] = __uint_as_float(f2tf((q1 * sn + q2 * cs) * 0.125f));

    const float k1 = base[DD + h*HD + d], k2 = base[DD + h*HD + d + 32];
    const float kr1 = k1 * cs - k2 * sn;
    const float kr2 = k1 * sn + k2 * cs;
    kout[ob + d]      = kr1;
    kout[ob + d + 32] = kr2;
    kh[ob + d]        = __uint_as_float(f2tf(kr1));
    kh[ob + d + 32]   = __uint_as_float(f2tf(kr2));

    const float v1 = base[2*DD + h*HD + d], v2 = base[2*DD + h*HD + d + 32];
    vout[ob + d]      = v1;
    vout[ob + d + 32] = v2;
    vh[ob + d]        = __uint_as_float(f2tf(v1));
    vh[ob + d + 32]   = __uint_as_float(f2tf(v2));
}

// ---------------------------------------------------------------------------
// Flash attention, tf32 mma.sync, causal. Br=Bc=64, 128 threads (4 warps).
// Warp w owns rows [w*16, w*16+16). All smem tiles stride 68 (conflict-free).
// smem: Qs | Ks[2] | Vt[2] (V transposed: [dim][token]) | Ps  = 6*64*68 floats.
// One __syncthreads per KV tile (K and V both double-buffered; P warp-private).
// ---------------------------------------------------------------------------
#define FSTR 68
#define FLASH_SMEM (6 * 64 * FSTR * 4)

__global__ __launch_bounds__(128) void flash_mma(
    const float* __restrict__ Q, const float* __restrict__ K,
    const float* __restrict__ V, float* __restrict__ ctx)
{
    extern __shared__ float sm[];
    float* Qs = sm;                      // 64*FSTR
    float* Ks = Qs + 64 * FSTR;          // [2][64*FSTR]
    float* Vt = Ks + 2 * 64 * FSTR;      // [2][64*FSTR]  (transposed V)
    float* Ps = Vt + 2 * 64 * FSTR;      // 64*FSTR
    const uint32_t Qs_u = smem_u32(Qs);
    const uint32_t Ks_u = smem_u32(Ks);

    const int qi   = gridDim.x - 1 - blockIdx.x;   // heavy tiles first
    const int bh   = blockIdx.y;         // 0..31
    const int tid  = threadIdx.x;
    const int lane = tid & 31;
    const int wid  = tid >> 5;
    const int lq   = lane >> 2;          // 0..7
    const int ls   = lane & 3;           // 0..3

    const float* Qb = Q + ((size_t)bh * LL + qi * 64) * HD;
    const float* Kb = K + (size_t)bh * LL * HD;
    const float* Vb = V + (size_t)bh * LL * HD;

#define FL_LOAD(dst_u, src)                                                   \
    {                                                                         \
        _Pragma("unroll")                                                     \
        for (int i = 0; i < 8; ++i) {                                         \
            const int c   = tid + i * 128;                                    \
            const int row = c >> 4;                                           \
            const int cc  = (c & 15) * 4;                                     \
            CP16((dst_u) + (uint32_t)(row * FSTR + cc) * 4,                   \
                 (src) + (size_t)row * HD + cc);                              \
        }                                                                     \
    }

    const int vtok  = tid & 63;          // V loader: one token per thread
    const int vhalf = tid >> 6;          // which 32 dims

    float4 vr[8];
#define FL_LDG_V(jt)                                                          \
    {                                                                         \
        const float* vb = Vb + ((size_t)(jt) * 64 + vtok) * HD + vhalf * 32;  \
        _Pragma("unroll")                                                     \
        for (int i = 0; i < 8; ++i) vr[i] = *(const float4*)(vb + i * 4);     \
    }

#define FL_STS_V(db)                                                          \
    {                                                                         \
        float* vt = Vt + (db) * 64 * FSTR;                                    \
        _Pragma("unroll")                                                     \
        for (int i = 0; i < 8; ++i) {                                         \
            const int c0 = vhalf * 32 + i * 4;                                \
            vt[(c0 + 0) * FSTR + vtok] = vr[i].x;                             \
            vt[(c0 + 1) * FSTR + vtok] = vr[i].y;                             \
            vt[(c0 + 2) * FSTR + vtok] = vr[i].z;                             \
            vt[(c0 + 3) * FSTR + vtok] = vr[i].w;                             \
        }                                                                     \
    }

    // prologue: Q + K0 in one cp.async group, V0 into regs
    FL_LOAD(Qs_u, Qb);
    FL_LOAD(Ks_u, Kb);
    CP_COMMIT();
    FL_LDG_V(0);

    float acc[8][4];
#pragma unroll
    for (int nt = 0; nt < 8; ++nt)
#pragma unroll
        for (int r = 0; r < 4; ++r) acc[nt][r] = 0.f;
    float m0 = -1e30f, m1 = -1e30f, l0 = 0.f, l1 = 0.f;

    const int rrow = wid * 16 + lq;      // this thread's row pair: rrow, rrow+8

    for (int jt = 0; jt <= qi; ++jt) {
        const int db = jt & 1;
        CP_WAIT(0);                      // K_jt (and Q on jt=0) in smem
        FL_STS_V(db);
        __syncthreads();                 // only barrier this iteration

        if (jt < qi) {                   // prefetch next K + V
            FL_LOAD(Ks_u + (uint32_t)((db ^ 1) * 64 * FSTR) * 4,
                    Kb + (size_t)(jt + 1) * 64 * HD);
            CP_COMMIT();
            FL_LDG_V(jt + 1);
        }

        // ---- S = Q K^T ----
        float sc[8][4];
#pragma unroll
        for (int nt = 0; nt < 8; ++nt)
#pragma unroll
            for (int r = 0; r < 4; ++r) sc[nt][r] = 0.f;

        const float* Kd = Ks + db * 64 * FSTR;
#pragma unroll
        for (int kb = 0; kb < 8; ++kb) {
            const int k = kb * 8 + ls;
            uint32_t a[4];
            a[0] = __float_as_uint(Qs[rrow * FSTR + k]);
            a[1] = __float_as_uint(Qs[(rrow + 8) * FSTR + k]);
            a[2] = __float_as_uint(Qs[rrow * FSTR + k + 4]);
            a[3] = __float_as_uint(Qs[(rrow + 8) * FSTR + k + 4]);
#pragma unroll
            for (int nt = 0; nt < 8; ++nt) {
                uint32_t b[2];
                const int cn = nt * 8 + lq;
                b[0] = __float_as_uint(Kd[cn * FSTR + k]);
                b[1] = __float_as_uint(Kd[cn * FSTR + k + 4]);
                mma8(sc[nt], a, b);
            }
        }

        // ---- causal mask on diagonal tile ----
        if (jt == qi) {
            const int rg0 = qi * 64 + rrow;
#pragma unroll
            for (int nt = 0; nt < 8; ++nt) {
                const int cg = jt * 64 + nt * 8 + ls * 2;
                if (cg > rg0)         sc[nt][0] += -1000000000.0f;
                if (cg + 1 > rg0)     sc[nt][1] += -1000000000.0f;
                if (cg > rg0 + 8)     sc[nt][2] += -1000000000.0f;
                if (cg + 1 > rg0 + 8) sc[nt][3] += -1000000000.0f;
            }
        }

        // ---- row max (thread-local + quad shfl) ----
        float mx0 = sc[0][0], mx1 = sc[0][2];
#pragma unroll
        for (int nt = 0; nt < 8; ++nt) {
            mx0 = fmaxf(mx0, fmaxf(sc[nt][0], sc[nt][1]));
            mx1 = fmaxf(mx1, fmaxf(sc[nt][2], sc[nt][3]));
        }
        mx0 = fmaxf(mx0, __shfl_xor_sync(0xffffffffu, mx0, 1));
        mx0 = fmaxf(mx0, __shfl_xor_sync(0xffffffffu, mx0, 2));
        mx1 = fmaxf(mx1, __shfl_xor_sync(0xffffffffu, mx1, 1));
        mx1 = fmaxf(mx1, __shfl_xor_sync(0xffffffffu, mx1, 2));

        const float mn0 = fmaxf(m0, mx0);
        const float mn1 = fmaxf(m1, mx1);
        const float al0 = __expf(m0 - mn0);
        const float al1 = __expf(m1 - mn1);
        m0 = mn0; m1 = mn1;

        // ---- P = exp(S - m), round, store to Ps; row sums ----
        float rs0 = 0.f, rs1 = 0.f;
#pragma unroll
        for (int nt = 0; nt < 8; ++nt) {
            const float p0 = __expf(sc[nt][0] - mn0);
            const float p1 = __expf(sc[nt][1] - mn0);
            const float p2 = __expf(sc[nt][2] - mn1);
            const float p3 = __expf(sc[nt][3] - mn1);
            rs0 += p0 + p1;  rs1 += p2 + p3;
            uint2 w0, w1;
            w0.x = f2tf(p0); w0.y = f2tf(p1);
            w1.x = f2tf(p2); w1.y = f2tf(p3);
            const int cc = nt * 8 + ls * 2;
            *(uint2*)(Ps + rrow * FSTR + cc)       = w0;
            *(uint2*)(Ps + (rrow + 8) * FSTR + cc) = w1;
        }
        rs0 += __shfl_xor_sync(0xffffffffu, rs0, 1);
        rs0 += __shfl_xor_sync(0xffffffffu, rs0, 2);
        rs1 += __shfl_xor_sync(0xffffffffu, rs1, 1);
        rs1 += __shfl_xor_sync(0xffffffffu, rs1, 2);
        l0 = l0 * al0 + rs0;
        l1 = l1 * al1 + rs1;

        // ---- rescale accumulators ----
#pragma unroll
        for (int nt = 0; nt < 8; ++nt) {
            acc[nt][0] *= al0; acc[nt][1] *= al0;
            acc[nt][2] *= al1; acc[nt][3] *= al1;
        }
        __syncwarp();

        // ---- O += P V ----
        const float* Vd = Vt + db * 64 * FSTR;
#pragma unroll
        for (int kb = 0; kb < 8; ++kb) {
            const int k = kb * 8 + ls;
            uint32_t a[4];
            a[0] = __float_as_uint(Ps[rrow * FSTR + k]);
            a[1] = __float_as_uint(Ps[(rrow + 8) * FSTR + k]);
            a[2] = __float_as_uint(Ps[rrow * FSTR + k + 4]);
            a[3] = __float_as_uint(Ps[(rrow + 8) * FSTR + k + 4]);
#pragma unroll
            for (int nt = 0; nt < 8; ++nt) {
                uint32_t b[2];
                const int cn = nt * 8 + lq;
                b[0] = __float_as_uint(Vd[cn * FSTR + k]);
                b[1] = __float_as_uint(Vd[cn * FSTR + k + 4]);
                mma8(acc[nt], a, b);
            }
        }
        __syncwarp();                    // Ps read-done before next iter's write
    }

    // ---- epilogue: O / l, round to tf32, write ctx (B,L,D) ----
    const float inv0 = 1.f / l0;
    const float inv1 = 1.f / l1;
    const int b = bh >> 4;
    const int h = bh & 15;
    const int r0 = qi * 64 + rrow;
#pragma unroll
    for (int nt = 0; nt < 8; ++nt) {
        const int cn = h * HD + nt * 8 + ls * 2;
        uint2 o0, o1;
        o0.x = f2tf(acc[nt][0] * inv0); o0.y = f2tf(acc[nt][1] * inv0);
        o1.x = f2tf(acc[nt][2] * inv1); o1.y = f2tf(acc[nt][3] * inv1);
        *(uint2*)(ctx + (size_t)(b * LL + r0) * DD + cn)     = o0;
        *(uint2*)(ctx + (size_t)(b * LL + r0 + 8) * DD + cn) = o1;
    }
}

// ---------------------------------------------------------------------------
// Launch
// ---------------------------------------------------------------------------
extern "C" void kernel_launch(void* const* d_in, const int* in_sizes, int n_in,
                              void* d_out, int out_size)
{
    const float* x       = (const float*)d_in[0];
    // d_in[1] = mask (deterministic triu(-1e9,1); applied analytically)
    const float* Wqkv_w  = (const float*)d_in[2];
    const float* Wqkv_b  = (const float*)d_in[3];
    const float* Wout_w  = (const float*)d_in[4];
    const float* Wout_b  = (const float*)d_in[5];

    float* out  = (float*)d_out;          // (B,L,D)
    float* kout = out + BLD;              // (B,H,L,hd)
    float* vout = kout + BLD;             // (B,H,L,hd)

    float *xr, *wqkv, *wout_r, *qkv, *qh, *kh, *vh, *ctx;
    cudaGetSymbolAddress((void**)&xr,     g_xr);
    cudaGetSymbolAddress((void**)&wqkv,   g_wqkv);
    cudaGetSymbolAddress((void**)&wout_r, g_wout);
    cudaGetSymbolAddress((void**)&qkv,    g_qkv);
    cudaGetSymbolAddress((void**)&qh,     g_q);
    cudaGetSymbolAddress((void**)&kh,     g_k);
    cudaGetSymbolAddress((void**)&vh,     g_v);
    cudaGetSymbolAddress((void**)&ctx,    g_ctx);

    cudaFuncSetAttribute(gemm_mma,
                         cudaFuncAttributeMaxDynamicSharedMemorySize, GEMM_SMEM);
    cudaFuncSetAttribute(flash_mma,
                         cudaFuncAttributeMaxDynamicSharedMemorySize, FLASH_SMEM);

    // 0) round all tf32 inputs in one launch
    round_all<<<(RND_TOTAL4 + 255) / 256, 256>>>(
        (const float4*)x, (float4*)xr,
        (const float4*)Wqkv_w, (float4*)wqkv,
        (const float4*)Wout_w, (float4*)wout_r);

    // 1) QKV projection: [4096,1024] x [3072,1024]^T
    gemm_mma<<<dim3(QKV_N / 128, ROWS / 128), 256, GEMM_SMEM>>>(
        xr, wqkv, Wqkv_b, qkv, QKV_N, DD);

    // 2) RoPE + head scatter (exact k,v -> d_out; rounded copies for flash)
    rope_scatter<<<(BB * LL * HH * 32) / 256, 256>>>(qkv, qh, kh, vh, kout, vout);

    // 3) Causal flash attention (tf32 mma)
    flash_mma<<<dim3(LL / 64, BB * HH), 128, FLASH_SMEM>>>(qh, kh, vh, ctx);

    // 4) Output projection: [4096,1024] x [1024,1024]^T
    gemm_mma<<<dim3(DD / 128, ROWS / 128), 256, GEMM_SMEM>>>(
        ctx, wout_r, Wout_b, out, DD, DD);
}

// round 5
// speedup vs baseline: 2.9462x; 1.0328x over previous
#include <cuda_runtime.h>
#include <cuda_bf16.h>
#include <cstdint>

// Problem shape constants (fixed by the reference).
#define BB 2
#define LL 2048
#define DD 1024
#define HH 16
#define HD 64
#define ROWS (BB*LL)            // 4096
#define QKV_N (3*DD)            // 3072
#define BLD (BB*LL*DD)          // 4194304
#define WQKV_SZ (QKV_N*DD)      // 3145728
#define WOUT_SZ (DD*DD)         // 1048576

// ---------------------------------------------------------------------------
// Scratch (alloc-free rule: __device__ globals)
// ---------------------------------------------------------------------------
__device__ float g_xr  [BLD];             // x rounded to tf32
__device__ float g_wqkv[WQKV_SZ];         // Wqkv rounded
__device__ float g_wout[WOUT_SZ];         // Wout rounded
__device__ float g_qkv [ROWS * QKV_N];    // qkv projection (fp32)
__device__ float g_q   [BLD];             // q heads, rope'd, scaled, rounded
__device__ float g_k   [BLD];             // k heads, rope'd, rounded
__device__ float g_v   [BLD];             // v heads, rounded
__device__ float g_ctx [BLD];             // attention context, rounded

// ---------------------------------------------------------------------------
// Helpers
// ---------------------------------------------------------------------------
__device__ __forceinline__ uint32_t f2tf(float f) {
    uint32_t r;
    asm("cvt.rna.tf32.f32 %0, %1;" : "=r"(r) : "f"(f));
    return r;
}

__device__ __forceinline__ uint32_t smem_u32(const void* p) {
    uint32_t a;
    asm("{ .reg .u64 t; cvta.to.shared.u64 t, %1; cvt.u32.u64 %0, t; }"
        : "=r"(a) : "l"(p));
    return a;
}

// m16n8k8 tf32 mma (.row.col)
__device__ __forceinline__ void mma8(float* c, const uint32_t* a, const uint32_t* b) {
    asm volatile(
        "mma.sync.aligned.m16n8k8.row.col.f32.tf32.tf32.f32 "
        "{%0,%1,%2,%3}, {%4,%5,%6,%7}, {%8,%9}, {%0,%1,%2,%3};"
        : "+f"(c[0]), "+f"(c[1]), "+f"(c[2]), "+f"(c[3])
        : "r"(a[0]), "r"(a[1]), "r"(a[2]), "r"(a[3]), "r"(b[0]), "r"(b[1]));
}

#define CP16(dst, src) \
    asm volatile("cp.async.cg.shared.global [%0], [%1], 16;" :: "r"(dst), "l"(src))
#define CP_COMMIT() asm volatile("cp.async.commit_group;" ::: "memory")
#define CP_WAIT(n)  asm volatile("cp.async.wait_group %0;" :: "n"(n) : "memory")

// ---------------------------------------------------------------------------
// Fused round-to-tf32 of x, Wqkv, Wout (one launch, float4)
// ---------------------------------------------------------------------------
#define RND_TOTAL4 ((BLD + WQKV_SZ + WOUT_SZ) / 4)

__global__ __launch_bounds__(256) void round_all(
    const float4* __restrict__ x,   float4* __restrict__ xr,
    const float4* __restrict__ wq,  float4* __restrict__ wqr,
    const float4* __restrict__ wo,  float4* __restrict__ wor)
{
    int i = blockIdx.x * 256 + threadIdx.x;
    if (i >= RND_TOTAL4) return;
    const float4* src; float4* dst;
    if (i < BLD/4)                       { src = x;  dst = xr;  }
    else if (i < (BLD + WQKV_SZ)/4)      { src = wq; dst = wqr; i -= BLD/4; }
    else                                 { src = wo; dst = wor; i -= (BLD + WQKV_SZ)/4; }
    float4 v = src[i];
    float4 o;
    o.x = __uint_as_float(f2tf(v.x));
    o.y = __uint_as_float(f2tf(v.y));
    o.z = __uint_as_float(f2tf(v.z));
    o.w = __uint_as_float(f2tf(v.w));
    dst[i] = o;
}

// ---------------------------------------------------------------------------
// tf32 mma.sync NT GEMM (unchanged from R4): 128x128 CTA tile, BK=32,
// 256 threads, 2x4 grid of 64x32 warp tiles, smem stride 36.
// ---------------------------------------------------------------------------
#define GSTR 36
#define GEMM_SMEM (2 * 2 * 128 * GSTR * 4)

__global__ __launch_bounds__(256) void gemm_mma(
    const float* __restrict__ A, const float* __restrict__ B,
    const float* __restrict__ bias, float* __restrict__ C,
    int N, int K)
{
    extern __shared__ float sm[];
    float* As = sm;
    float* Bs = sm + 2 * 128 * GSTR;
    const uint32_t As_u = smem_u32(As);
    const uint32_t Bs_u = smem_u32(Bs);

    const int tid  = threadIdx.x;
    const int lane = tid & 31;
    const int wid  = tid >> 5;
    const int wm   = wid & 1;
    const int wn   = wid >> 1;
    const int lq   = lane >> 2;
    const int ls   = lane & 3;

    const float* Ab = A + (size_t)(blockIdx.y * 128) * K;
    const float* Bb = B + (size_t)(blockIdx.x * 128) * K;
    const int KS = K >> 5;

    float acc[4][4][4];
#pragma unroll
    for (int mt = 0; mt < 4; ++mt)
#pragma unroll
        for (int nt = 0; nt < 4; ++nt)
#pragma unroll
            for (int r = 0; r < 4; ++r) acc[mt][nt][r] = 0.f;

#define GEMM_LOAD(ks, db)                                                     \
    {                                                                         \
        const int k0 = (ks) * 32;                                             \
        const uint32_t dA = As_u + (db) * 128 * GSTR * 4;                     \
        const uint32_t dB = Bs_u + (db) * 128 * GSTR * 4;                     \
        _Pragma("unroll")                                                     \
        for (int i = 0; i < 4; ++i) {                                         \
            const int c   = tid + i * 256;                                    \
            const int row = c >> 3;                                           \
            const int cc  = (c & 7) * 4;                                      \
            const uint32_t off = (uint32_t)(row * GSTR + cc) * 4;             \
            CP16(dA + off, Ab + (size_t)row * K + k0 + cc);                   \
            CP16(dB + off, Bb + (size_t)row * K + k0 + cc);                   \
        }                                                                     \
        CP_COMMIT();                                                          \
    }

    GEMM_LOAD(0, 0);

    for (int ks = 0; ks < KS; ++ks) {
        const int db = ks & 1;
        if (ks + 1 < KS) { GEMM_LOAD(ks + 1, db ^ 1); CP_WAIT(1); }
        else             { CP_WAIT(0); }
        __syncthreads();

        const float* Ad = As + db * 128 * GSTR;
        const float* Bd = Bs + db * 128 * GSTR;

#pragma unroll
        for (int kb = 0; kb < 4; ++kb) {
            const int k = kb * 8 + ls;
            uint32_t a[4][4], b[4][2];
#pragma unroll
            for (int mt = 0; mt < 4; ++mt) {
                const int r = wm * 64 + mt * 16 + lq;
                a[mt][0] = __float_as_uint(Ad[r * GSTR + k]);
                a[mt][1] = __float_as_uint(Ad[(r + 8) * GSTR + k]);
                a[mt][2] = __float_as_uint(Ad[r * GSTR + k + 4]);
                a[mt][3] = __float_as_uint(Ad[(r + 8) * GSTR + k + 4]);
            }
#pragma unroll
            for (int nt = 0; nt < 4; ++nt) {
                const int cn = wn * 32 + nt * 8 + lq;
                b[nt][0] = __float_as_uint(Bd[cn * GSTR + k]);
                b[nt][1] = __float_as_uint(Bd[cn * GSTR + k + 4]);
            }
#pragma unroll
            for (int mt = 0; mt < 4; ++mt)
#pragma unroll
                for (int nt = 0; nt < 4; ++nt)
                    mma8(acc[mt][nt], a[mt], b[nt]);
        }
        __syncthreads();
    }

    const int row_base = blockIdx.y * 128 + wm * 64;
    const int col_base = blockIdx.x * 128 + wn * 32;
#pragma unroll
    for (int mt = 0; mt < 4; ++mt) {
        const int r0 = row_base + mt * 16 + lq;
#pragma unroll
        for (int nt = 0; nt < 4; ++nt) {
            const int cn = col_base + nt * 8 + ls * 2;
            const float2 bb = *(const float2*)(bias + cn);
            float2 o0, o1;
            o0.x = acc[mt][nt][0] + bb.x;  o0.y = acc[mt][nt][1] + bb.y;
            o1.x = acc[mt][nt][2] + bb.x;  o1.y = acc[mt][nt][3] + bb.y;
            *(float2*)(C + (size_t)r0 * N + cn)       = o0;
            *(float2*)(C + (size_t)(r0 + 8) * N + cn) = o1;
        }
    }
}

// ---------------------------------------------------------------------------
// RoPE + head scatter (unchanged).
// ---------------------------------------------------------------------------
__global__ __launch_bounds__(256) void rope_scatter(
    const float* __restrict__ qkv,
    float* __restrict__ qh, float* __restrict__ kh, float* __restrict__ vh,
    float* __restrict__ kout, float* __restrict__ vout)
{
    const int t = blockIdx.x * blockDim.x + threadIdx.x;
    const int d = t & 31;
    const int h = (t >> 5) & 15;
    const int l = (t >> 9) & 2047;
    const int b = t >> 20;

    const float* base = qkv + (size_t)(b * LL + l) * QKV_N;

    const float inv = __expf(-(float)d * (9.210340371976184f / 32.f));
    const float ang = (float)l * inv;
    float sn, cs;
    sincosf(ang, &sn, &cs);

    const size_t ob = ((size_t)((b * HH + h) * LL + l)) * HD;

    const float q1 = base[h*HD + d], q2 = base[h*HD + d + 32];
    qh[ob + d]      = __uint_as_float(f2tf((q1 * cs - q2 * sn) * 0.125f));
    qh[ob + d + 32] = __uint_as_float(f2tf((q1 * sn + q2 * cs) * 0.125f));

    const float k1 = base[DD + h*HD + d], k2 = base[DD + h*HD + d + 32];
    const float kr1 = k1 * cs - k2 * sn;
    const float kr2 = k1 * sn + k2 * cs;
    kout[ob + d]      = kr1;
    kout[ob + d + 32] = kr2;
    kh[ob + d]        = __uint_as_float(f2tf(kr1));
    kh[ob + d + 32]   = __uint_as_float(f2tf(kr2));

    const float v1 = base[2*DD + h*HD + d], v2 = base[2*DD + h*HD + d + 32];
    vout[ob + d]      = v1;
    vout[ob + d + 32] = v2;
    vh[ob + d]        = __uint_as_float(f2tf(v1));
    vh[ob + d + 32]   = __uint_as_float(f2tf(v2));
}

// ---------------------------------------------------------------------------
// Flash attention v2: Br=128, Bc=64, 256 threads (8 warps, 16 rows each).
// Q fragments register-resident (loaded straight from gmem).
// smem: Ps[128*FSTR] | Ks[2][64*FSTR] | Vt[2][64*FSTR]  (stride 68).
// ---------------------------------------------------------------------------
#define FSTR 68
#define FLASH_SMEM ((128 + 2*64 + 2*64) * FSTR * 4)   // 104448 B

__global__ __launch_bounds__(256) void flash_mma(
    const float* __restrict__ Q, const float* __restrict__ K,
    const float* __restrict__ V, float* __restrict__ ctx)
{
    extern __shared__ float sm[];
    float* Ps = sm;                      // 128*FSTR
    float* Ks = Ps + 128 * FSTR;         // [2][64*FSTR]
    float* Vt = Ks + 2 * 64 * FSTR;      // [2][64*FSTR]  (transposed V)
    const uint32_t Ks_u = smem_u32(Ks);

    const int qi   = gridDim.x - 1 - blockIdx.x;   // heavy tiles first
    const int bh   = blockIdx.y;         // 0..31
    const int tid  = threadIdx.x;
    const int lane = tid & 31;
    const int wid  = tid >> 5;           // 0..7
    const int lq   = lane >> 2;          // 0..7
    const int ls   = lane & 3;           // 0..3
    const int rrow = wid * 16 + lq;      // rows rrow, rrow+8 (0..127)

    const float* Qb = Q + ((size_t)bh * LL + qi * 128) * HD;
    const float* Kb = K + (size_t)bh * LL * HD;
    const float* Vb = V + (size_t)bh * LL * HD;

    // K tile loader: 64x64 floats, 256 threads -> 4 cp.async each
#define FL_LOAD_K(dst_u, src)                                                 \
    {                                                                         \
        _Pragma("unroll")                                                     \
        for (int i = 0; i < 4; ++i) {                                         \
            const int c   = tid + i * 256;                                    \
            const int row = c >> 4;                                           \
            const int cc  = (c & 15) * 4;                                     \
            CP16((dst_u) + (uint32_t)(row * FSTR + cc) * 4,                   \
                 (src) + (size_t)row * HD + cc);                              \
        }                                                                     \
    }

    const int vtok  = tid & 63;          // token within tile
    const int vhalf = tid >> 6;          // 0..3 -> 16 dims each

    float4 vr[4];
#define FL_LDG_V(jt)                                                          \
    {                                                                         \
        const float* vb = Vb + ((size_t)(jt) * 64 + vtok) * HD + vhalf * 16;  \
        _Pragma("unroll")                                                     \
        for (int i = 0; i < 4; ++i) vr[i] = *(const float4*)(vb + i * 4);     \
    }

#define FL_STS_V(db)                                                          \
    {                                                                         \
        float* vt = Vt + (db) * 64 * FSTR;                                    \
        _Pragma("unroll")                                                     \
        for (int i = 0; i < 4; ++i) {                                         \
            const int c0 = vhalf * 16 + i * 4;                                \
            vt[(c0 + 0) * FSTR + vtok] = vr[i].x;                             \
            vt[(c0 + 1) * FSTR + vtok] = vr[i].y;                             \
            vt[(c0 + 2) * FSTR + vtok] = vr[i].z;                             \
            vt[(c0 + 3) * FSTR + vtok] = vr[i].w;                             \
        }                                                                     \
    }

    // prologue: K0 via cp.async, V0 via LDG, Q fragments straight from gmem
    FL_LOAD_K(Ks_u, Kb);
    CP_COMMIT();
    FL_LDG_V(0);

    uint32_t qf[8][4];
#pragma unroll
    for (int kb = 0; kb < 8; ++kb) {
        const int k = kb * 8 + ls;
        qf[kb][0] = __float_as_uint(Qb[(size_t)rrow * HD + k]);
        qf[kb][1] = __float_as_uint(Qb[(size_t)(rrow + 8) * HD + k]);
        qf[kb][2] = __float_as_uint(Qb[(size_t)rrow * HD + k + 4]);
        qf[kb][3] = __float_as_uint(Qb[(size_t)(rrow + 8) * HD + k + 4]);
    }

    float acc[8][4];
#pragma unroll
    for (int nt = 0; nt < 8; ++nt)
#pragma unroll
        for (int r = 0; r < 4; ++r) acc[nt][r] = 0.f;
    float m0 = -1e30f, m1 = -1e30f, l0 = 0.f, l1 = 0.f;

    const int jtmax = 2 * qi + 1;

    for (int jt = 0; jt <= jtmax; ++jt) {
        const int db = jt & 1;
        CP_WAIT(0);                      // K_jt in smem
        FL_STS_V(db);
        __syncthreads();                 // only barrier this iteration

        if (jt < jtmax) {                // prefetch next K + V
            FL_LOAD_K(Ks_u + (uint32_t)((db ^ 1) * 64 * FSTR) * 4,
                      Kb + (size_t)(jt + 1) * 64 * HD);
            CP_COMMIT();
            FL_LDG_V(jt + 1);
        }

        // ---- S = Q K^T ----
        float sc[8][4];
#pragma unroll
        for (int nt = 0; nt < 8; ++nt)
#pragma unroll
            for (int r = 0; r < 4; ++r) sc[nt][r] = 0.f;

        const float* Kd = Ks + db * 64 * FSTR;
#pragma unroll
        for (int kb = 0; kb < 8; ++kb) {
            const int k = kb * 8 + ls;
#pragma unroll
            for (int nt = 0; nt < 8; ++nt) {
                uint32_t b[2];
                const int cn = nt * 8 + lq;
                b[0] = __float_as_uint(Kd[cn * FSTR + k]);
                b[1] = __float_as_uint(Kd[cn * FSTR + k + 4]);
                mma8(sc[nt], qf[kb], b);
            }
        }

        // ---- causal mask (last two tiles touch/straddle the diagonal) ----
        if (jt >= 2 * qi) {
            const int rg0 = qi * 128 + rrow;
#pragma unroll
            for (int nt = 0; nt < 8; ++nt) {
                const int cg = jt * 64 + nt * 8 + ls * 2;
                if (cg > rg0)         sc[nt][0] += -1000000000.0f;
                if (cg + 1 > rg0)     sc[nt][1] += -1000000000.0f;
                if (cg > rg0 + 8)     sc[nt][2] += -1000000000.0f;
                if (cg + 1 > rg0 + 8) sc[nt][3] += -1000000000.0f;
            }
        }

        // ---- row max (thread-local + quad shfl) ----
        float mx0 = sc[0][0], mx1 = sc[0][2];
#pragma unroll
        for (int nt = 0; nt < 8; ++nt) {
            mx0 = fmaxf(mx0, fmaxf(sc[nt][0], sc[nt][1]));
            mx1 = fmaxf(mx1, fmaxf(sc[nt][2], sc[nt][3]));
        }
        mx0 = fmaxf(mx0, __shfl_xor_sync(0xffffffffu, mx0, 1));
        mx0 = fmaxf(mx0, __shfl_xor_sync(0xffffffffu, mx0, 2));
        mx1 = fmaxf(mx1, __shfl_xor_sync(0xffffffffu, mx1, 1));
        mx1 = fmaxf(mx1, __shfl_xor_sync(0xffffffffu, mx1, 2));

        const float mn0 = fmaxf(m0, mx0);
        const float mn1 = fmaxf(m1, mx1);
        const float al0 = __expf(m0 - mn0);
        const float al1 = __expf(m1 - mn1);
        m0 = mn0; m1 = mn1;

        // ---- P = exp(S - m), round, store to Ps; row sums ----
        float rs0 = 0.f, rs1 = 0.f;
#pragma unroll
        for (int nt = 0; nt < 8; ++nt) {
            const float p0 = __expf(sc[nt][0] - mn0);
            const float p1 = __expf(sc[nt][1] - mn0);
            const float p2 = __expf(sc[nt][2] - mn1);
            const float p3 = __expf(sc[nt][3] - mn1);
            rs0 += p0 + p1;  rs1 += p2 + p3;
            uint2 w0, w1;
            w0.x = f2tf(p0); w0.y = f2tf(p1);
            w1.x = f2tf(p2); w1.y = f2tf(p3);
            const int cc = nt * 8 + ls * 2;
            *(uint2*)(Ps + rrow * FSTR + cc)       = w0;
            *(uint2*)(Ps + (rrow + 8) * FSTR + cc) = w1;
        }
        rs0 += __shfl_xor_sync(0xffffffffu, rs0, 1);
        rs0 += __shfl_xor_sync(0xffffffffu, rs0, 2);
        rs1 += __shfl_xor_sync(0xffffffffu, rs1, 1);
        rs1 += __shfl_xor_sync(0xffffffffu, rs1, 2);
        l0 = l0 * al0 + rs0;
        l1 = l1 * al1 + rs1;

        // ---- rescale accumulators ----
#pragma unroll
        for (int nt = 0; nt < 8; ++nt) {
            acc[nt][0] *= al0; acc[nt][1] *= al0;
            acc[nt][2] *= al1; acc[nt][3] *= al1;
        }
        __syncwarp();

        // ---- O += P V ----
        const float* Vd = Vt + db * 64 * FSTR;
#pragma unroll
        for (int kb = 0; kb < 8; ++kb) {
            const int k = kb * 8 + ls;
            uint32_t a[4];
            a[0] = __float_as_uint(Ps[rrow * FSTR + k]);
            a[1] = __float_as_uint(Ps[(rrow + 8) * FSTR + k]);
            a[2] = __float_as_uint(Ps[rrow * FSTR + k + 4]);
            a[3] = __float_as_uint(Ps[(rrow + 8) * FSTR + k + 4]);
#pragma unroll
            for (int nt = 0; nt < 8; ++nt) {
                uint32_t b[2];
                const int cn = nt * 8 + lq;
                b[0] = __float_as_uint(Vd[cn * FSTR + k]);
                b[1] = __float_as_uint(Vd[cn * FSTR + k + 4]);
                mma8(acc[nt], a, b);
            }
        }
        __syncwarp();                    // Ps read-done before next iter's write
    }

    // ---- epilogue: O / l, round to tf32, write ctx (B,L,D) ----
    const float inv0 = 1.f / l0;
    const float inv1 = 1.f / l1;
    const int b = bh >> 4;
    const int h = bh & 15;
    const int r0 = qi * 128 + rrow;
#pragma unroll
    for (int nt = 0; nt < 8; ++nt) {
        const int cn = h * HD + nt * 8 + ls * 2;
        uint2 o0, o1;
        o0.x = f2tf(acc[nt][0] * inv0); o0.y = f2tf(acc[nt][1] * inv0);
        o1.x = f2tf(acc[nt][2] * inv1); o1.y = f2tf(acc[nt][3] * inv1);
        *(uint2*)(ctx + (size_t)(b * LL + r0) * DD + cn)     = o0;
        *(uint2*)(ctx + (size_t)(b * LL + r0 + 8) * DD + cn) = o1;
    }
}

// ---------------------------------------------------------------------------
// Launch
// ---------------------------------------------------------------------------
extern "C" void kernel_launch(void* const* d_in, const int* in_sizes, int n_in,
                              void* d_out, int out_size)
{
    const float* x       = (const float*)d_in[0];
    // d_in[1] = mask (deterministic triu(-1e9,1); applied analytically)
    const float* Wqkv_w  = (const float*)d_in[2];
    const float* Wqkv_b  = (const float*)d_in[3];
    const float* Wout_w  = (const float*)d_in[4];
    const float* Wout_b  = (const float*)d_in[5];

    float* out  = (float*)d_out;          // (B,L,D)
    float* kout = out + BLD;              // (B,H,L,hd)
    float* vout = kout + BLD;             // (B,H,L,hd)

    float *xr, *wqkv, *wout_r, *qkv, *qh, *kh, *vh, *ctx;
    cudaGetSymbolAddress((void**)&xr,     g_xr);
    cudaGetSymbolAddress((void**)&wqkv,   g_wqkv);
    cudaGetSymbolAddress((void**)&wout_r, g_wout);
    cudaGetSymbolAddress((void**)&qkv,    g_qkv);
    cudaGetSymbolAddress((void**)&qh,     g_q);
    cudaGetSymbolAddress((void**)&kh,     g_k);
    cudaGetSymbolAddress((void**)&vh,     g_v);
    cudaGetSymbolAddress((void**)&ctx,    g_ctx);

    cudaFuncSetAttribute(gemm_mma,
                         cudaFuncAttributeMaxDynamicSharedMemorySize, GEMM_SMEM);
    cudaFuncSetAttribute(flash_mma,
                         cudaFuncAttributeMaxDynamicSharedMemorySize, FLASH_SMEM);

    // 0) round all tf32 inputs in one launch
    round_all<<<(RND_TOTAL4 + 255) / 256, 256>>>(
        (const float4*)x, (float4*)xr,
        (const float4*)Wqkv_w, (float4*)wqkv,
        (const float4*)Wout_w, (float4*)wout_r);

    // 1) QKV projection: [4096,1024] x [3072,1024]^T
    gemm_mma<<<dim3(QKV_N / 128, ROWS / 128), 256, GEMM_SMEM>>>(
        xr, wqkv, Wqkv_b, qkv, QKV_N, DD);

    // 2) RoPE + head scatter (exact k,v -> d_out; rounded copies for flash)
    rope_scatter<<<(BB * LL * HH * 32) / 256, 256>>>(qkv, qh, kh, vh, kout, vout);

    // 3) Causal flash attention (tf32 mma, Br=128)
    flash_mma<<<dim3(LL / 128, BB * HH), 256, FLASH_SMEM>>>(qh, kh, vh, ctx);

    // 4) Output projection: [4096,1024] x [1024,1024]^T
    gemm_mma<<<dim3(DD / 128, ROWS / 128), 256, GEMM_SMEM>>>(
        ctx, wout_r, Wout_b, out, DD, DD);
}

// round 6
// speedup vs baseline: 3.0955x; 1.0507x over previous
#include <cuda_runtime.h>
#include <cuda_bf16.h>
#include <cstdint>

// Problem shape constants (fixed by the reference).
#define BB 2
#define LL 2048
#define DD 1024
#define HH 16
#define HD 64
#define ROWS (BB*LL)            // 4096
#define QKV_N (3*DD)            // 3072
#define BLD (BB*LL*DD)          // 4194304
#define WQKV_SZ (QKV_N*DD)      // 3145728
#define WOUT_SZ (DD*DD)         // 1048576

// ---------------------------------------------------------------------------
// Scratch (alloc-free rule: __device__ globals)
// ---------------------------------------------------------------------------
__device__ float g_xr  [BLD];
__device__ float g_wqkv[WQKV_SZ];
__device__ float g_wout[WOUT_SZ];
__device__ float g_qkv [ROWS * QKV_N];
__device__ float g_q   [BLD];
__device__ float g_k   [BLD];
__device__ float g_v   [BLD];
__device__ float g_ctx [BLD];

// ---------------------------------------------------------------------------
// Helpers
// ---------------------------------------------------------------------------
__device__ __forceinline__ uint32_t f2tf(float f) {
    uint32_t r;
    asm("cvt.rna.tf32.f32 %0, %1;" : "=r"(r) : "f"(f));
    return r;
}

__device__ __forceinline__ uint32_t smem_u32(const void* p) {
    uint32_t a;
    asm("{ .reg .u64 t; cvta.to.shared.u64 t, %1; cvt.u32.u64 %0, t; }"
        : "=r"(a) : "l"(p));
    return a;
}

// m16n8k8 tf32 mma (.row.col)
__device__ __forceinline__ void mma8(float* c, const uint32_t* a, const uint32_t* b) {
    asm volatile(
        "mma.sync.aligned.m16n8k8.row.col.f32.tf32.tf32.f32 "
        "{%0,%1,%2,%3}, {%4,%5,%6,%7}, {%8,%9}, {%0,%1,%2,%3};"
        : "+f"(c[0]), "+f"(c[1]), "+f"(c[2]), "+f"(c[3])
        : "r"(a[0]), "r"(a[1]), "r"(a[2]), "r"(a[3]), "r"(b[0]), "r"(b[1]));
}

// ldmatrix x4 (b32 data viewed as b16 pairs; mapping matches mma frags)
__device__ __forceinline__ void ldsm4(uint32_t* r, uint32_t addr) {
    asm volatile(
        "ldmatrix.sync.aligned.m8n8.x4.shared.b16 {%0,%1,%2,%3}, [%4];"
        : "=r"(r[0]), "=r"(r[1]), "=r"(r[2]), "=r"(r[3]) : "r"(addr));
}

#define CP16(dst, src) \
    asm volatile("cp.async.cg.shared.global [%0], [%1], 16;" :: "r"(dst), "l"(src))
#define CP_COMMIT() asm volatile("cp.async.commit_group;" ::: "memory")
#define CP_WAIT(n)  asm volatile("cp.async.wait_group %0;" :: "n"(n) : "memory")

// ---------------------------------------------------------------------------
// Fused round-to-tf32 of x, Wqkv, Wout
// ---------------------------------------------------------------------------
#define RND_TOTAL4 ((BLD + WQKV_SZ + WOUT_SZ) / 4)

__global__ __launch_bounds__(256) void round_all(
    const float4* __restrict__ x,   float4* __restrict__ xr,
    const float4* __restrict__ wq,  float4* __restrict__ wqr,
    const float4* __restrict__ wo,  float4* __restrict__ wor)
{
    int i = blockIdx.x * 256 + threadIdx.x;
    if (i >= RND_TOTAL4) return;
    const float4* src; float4* dst;
    if (i < BLD/4)                       { src = x;  dst = xr;  }
    else if (i < (BLD + WQKV_SZ)/4)      { src = wq; dst = wqr; i -= BLD/4; }
    else                                 { src = wo; dst = wor; i -= (BLD + WQKV_SZ)/4; }
    float4 v = src[i];
    float4 o;
    o.x = __uint_as_float(f2tf(v.x));
    o.y = __uint_as_float(f2tf(v.y));
    o.z = __uint_as_float(f2tf(v.z));
    o.w = __uint_as_float(f2tf(v.w));
    dst[i] = o;
}

// ---------------------------------------------------------------------------
// tf32 mma.sync NT GEMM, ldmatrix fragment loads.
// 128x128 CTA tile, BK=32, 256 threads, 2x4 warp grid of 64x32 tiles.
// smem pad stride 36 (144B rows = 9*16B -> ldmatrix conflict-free).
// ---------------------------------------------------------------------------
#define GSTR 36
#define GEMM_SMEM (2 * 2 * 128 * GSTR * 4)

__global__ __launch_bounds__(256) void gemm_mma(
    const float* __restrict__ A, const float* __restrict__ B,
    const float* __restrict__ bias, float* __restrict__ C,
    int N, int K)
{
    extern __shared__ float sm[];
    float* As = sm;
    float* Bs = sm + 2 * 128 * GSTR;
    const uint32_t As_u = smem_u32(As);
    const uint32_t Bs_u = smem_u32(Bs);

    const int tid  = threadIdx.x;
    const int lane = tid & 31;
    const int wid  = tid >> 5;
    const int wm   = wid & 1;
    const int wn   = wid >> 1;
    const int lq   = lane >> 2;
    const int ls   = lane & 3;
    const int s    = lane >> 3;          // ldmatrix submatrix id
    const int srow = lane & 7;           // ldmatrix row within submatrix

    // per-lane ldmatrix base offsets (bytes)
    // A subs: (s&1) -> +8 rows, (s>>1) -> +4 k
    const uint32_t a_lane =
        (uint32_t)(((wm * 64) + (s & 1) * 8 + srow) * GSTR + (s >> 1) * 4) * 4;
    // B subs: (s>>1) -> +8 cols(n), (s&1) -> +4 k
    const uint32_t b_lane =
        (uint32_t)(((wn * 32) + (s >> 1) * 8 + srow) * GSTR + (s & 1) * 4) * 4;

    const float* Ab = A + (size_t)(blockIdx.y * 128) * K;
    const float* Bb = B + (size_t)(blockIdx.x * 128) * K;
    const int KS = K >> 5;

    float acc[4][4][4];
#pragma unroll
    for (int mt = 0; mt < 4; ++mt)
#pragma unroll
        for (int nt = 0; nt < 4; ++nt)
#pragma unroll
            for (int r = 0; r < 4; ++r) acc[mt][nt][r] = 0.f;

#define GEMM_LOAD(ks, db)                                                     \
    {                                                                         \
        const int k0 = (ks) * 32;                                             \
        const uint32_t dA = As_u + (db) * 128 * GSTR * 4;                     \
        const uint32_t dB = Bs_u + (db) * 128 * GSTR * 4;                     \
        _Pragma("unroll")                                                     \
        for (int i = 0; i < 4; ++i) {                                         \
            const int c   = tid + i * 256;                                    \
            const int row = c >> 3;                                           \
            const int cc  = (c & 7) * 4;                                      \
            const uint32_t off = (uint32_t)(row * GSTR + cc) * 4;             \
            CP16(dA + off, Ab + (size_t)row * K + k0 + cc);                   \
            CP16(dB + off, Bb + (size_t)row * K + k0 + cc);                   \
        }                                                                     \
        CP_COMMIT();                                                          \
    }

    GEMM_LOAD(0, 0);

    for (int ks = 0; ks < KS; ++ks) {
        const int db = ks & 1;
        if (ks + 1 < KS) { GEMM_LOAD(ks + 1, db ^ 1); CP_WAIT(1); }
        else             { CP_WAIT(0); }
        __syncthreads();

        const uint32_t Ad_u = As_u + db * 128 * GSTR * 4;
        const uint32_t Bd_u = Bs_u + db * 128 * GSTR * 4;

#pragma unroll
        for (int kb = 0; kb < 4; ++kb) {
            uint32_t a[4][4], b[2][4];
#pragma unroll
            for (int mt = 0; mt < 4; ++mt)
                ldsm4(a[mt], Ad_u + a_lane + (uint32_t)(mt * 16 * GSTR + kb * 8) * 4);
#pragma unroll
            for (int ntp = 0; ntp < 2; ++ntp)
                ldsm4(b[ntp], Bd_u + b_lane + (uint32_t)(ntp * 16 * GSTR + kb * 8) * 4);
#pragma unroll
            for (int mt = 0; mt < 4; ++mt)
#pragma unroll
                for (int nt = 0; nt < 4; ++nt)
                    mma8(acc[mt][nt], a[mt], &b[nt >> 1][(nt & 1) * 2]);
        }
        __syncthreads();
    }

    const int row_base = blockIdx.y * 128 + wm * 64;
    const int col_base = blockIdx.x * 128 + wn * 32;
#pragma unroll
    for (int mt = 0; mt < 4; ++mt) {
        const int r0 = row_base + mt * 16 + lq;
#pragma unroll
        for (int nt = 0; nt < 4; ++nt) {
            const int cn = col_base + nt * 8 + ls * 2;
            const float2 bb = *(const float2*)(bias + cn);
            float2 o0, o1;
            o0.x = acc[mt][nt][0] + bb.x;  o0.y = acc[mt][nt][1] + bb.y;
            o1.x = acc[mt][nt][2] + bb.x;  o1.y = acc[mt][nt][3] + bb.y;
            *(float2*)(C + (size_t)r0 * N + cn)       = o0;
            *(float2*)(C + (size_t)(r0 + 8) * N + cn) = o1;
        }
    }
}

// ---------------------------------------------------------------------------
// RoPE + head scatter (unchanged).
// ---------------------------------------------------------------------------
__global__ __launch_bounds__(256) void rope_scatter(
    const float* __restrict__ qkv,
    float* __restrict__ qh, float* __restrict__ kh, float* __restrict__ vh,
    float* __restrict__ kout, float* __restrict__ vout)
{
    const int t = blockIdx.x * blockDim.x + threadIdx.x;
    const int d = t & 31;
    const int h = (t >> 5) & 15;
    const int l = (t >> 9) & 2047;
    const int b = t >> 20;

    const float* base = qkv + (size_t)(b * LL + l) * QKV_N;

    const float inv = __expf(-(float)d * (9.210340371976184f / 32.f));
    const float ang = (float)l * inv;
    float sn, cs;
    sincosf(ang, &sn, &cs);

    const size_t ob = ((size_t)((b * HH + h) * LL + l)) * HD;

    const float q1 = base[h*HD + d], q2 = base[h*HD + d + 32];
    qh[ob + d]      = __uint_as_float(f2tf((q1 * cs - q2 * sn) * 0.125f));
    qh[ob + d + 32] = __uint_as_float(f2tf((q1 * sn + q2 * cs) * 0.125f));

    const float k1 = base[DD + h*HD + d], k2 = base[DD + h*HD + d + 32];
    const float kr1 = k1 * cs - k2 * sn;
    const float kr2 = k1 * sn + k2 * cs;
    kout[ob + d]      = kr1;
    kout[ob + d + 32] = kr2;
    kh[ob + d]        = __uint_as_float(f2tf(kr1));
    kh[ob + d + 32]   = __uint_as_float(f2tf(kr2));

    const float v1 = base[2*DD + h*HD + d], v2 = base[2*DD + h*HD + d + 32];
    vout[ob + d]      = v1;
    vout[ob + d + 32] = v2;
    vh[ob + d]        = __uint_as_float(f2tf(v1));
    vh[ob + d + 32]   = __uint_as_float(f2tf(v2));
}

// ---------------------------------------------------------------------------
// Flash attention v3: Br=128, Bc=64, 256 threads, ldmatrix fragment loads.
// Q fragments register-resident. smem stride 68 (272B = 17*16B rows).
// smem: Ps[128*FSTR] | Ks[2][64*FSTR] | Vt[2][64*FSTR].
// ---------------------------------------------------------------------------
#define FSTR 68
#define FLASH_SMEM ((128 + 2*64 + 2*64) * FSTR * 4)   // 104448 B

__global__ __launch_bounds__(256) void flash_mma(
    const float* __restrict__ Q, const float* __restrict__ K,
    const float* __restrict__ V, float* __restrict__ ctx)
{
    extern __shared__ float sm[];
    float* Ps = sm;                      // 128*FSTR
    float* Ks = Ps + 128 * FSTR;         // [2][64*FSTR]
    float* Vt = Ks + 2 * 64 * FSTR;      // [2][64*FSTR]  (transposed V)
    const uint32_t Ps_u = smem_u32(Ps);
    const uint32_t Ks_u = smem_u32(Ks);
    const uint32_t Vt_u = smem_u32(Vt);

    const int qi   = gridDim.x - 1 - blockIdx.x;   // heavy tiles first
    const int bh   = blockIdx.y;
    const int tid  = threadIdx.x;
    const int lane = tid & 31;
    const int wid  = tid >> 5;           // 0..7
    const int lq   = lane >> 2;
    const int ls   = lane & 3;
    const int s    = lane >> 3;          // ldmatrix submatrix id
    const int srow = lane & 7;
    const int rrow = wid * 16 + lq;      // rows rrow, rrow+8 (0..127)

    // ldmatrix per-lane offsets (bytes):
    // B-frags (K / V tiles): (s>>1) -> +8 n, (s&1) -> +4 k
    const uint32_t bk_lane =
        (uint32_t)(((s >> 1) * 8 + srow) * FSTR + (s & 1) * 4) * 4;
    // A-frags (P tile): (s&1) -> +8 rows, (s>>1) -> +4 k
    const uint32_t ap_lane =
        (uint32_t)(((s & 1) * 8 + srow) * FSTR + (s >> 1) * 4) * 4;
    const uint32_t Ps_warp = Ps_u + (uint32_t)(wid * 16 * FSTR) * 4;

    const float* Qb = Q + ((size_t)bh * LL + qi * 128) * HD;
    const float* Kb = K + (size_t)bh * LL * HD;
    const float* Vb = V + (size_t)bh * LL * HD;

#define FL_LOAD_K(dst_u, src)                                                 \
    {                                                                         \
        _Pragma("unroll")                                                     \
        for (int i = 0; i < 4; ++i) {                                         \
            const int c   = tid + i * 256;                                    \
            const int row = c >> 4;                                           \
            const int cc  = (c & 15) * 4;                                     \
            CP16((dst_u) + (uint32_t)(row * FSTR + cc) * 4,                   \
                 (src) + (size_t)row * HD + cc);                              \
        }                                                                     \
    }

    const int vtok  = tid & 63;
    const int vhalf = tid >> 6;

    float4 vr[4];
#define FL_LDG_V(jt)                                                          \
    {                                                                         \
        const float* vb = Vb + ((size_t)(jt) * 64 + vtok) * HD + vhalf * 16;  \
        _Pragma("unroll")                                                     \
        for (int i = 0; i < 4; ++i) vr[i] = *(const float4*)(vb + i * 4);     \
    }

#define FL_STS_V(db)                                                          \
    {                                                                         \
        float* vt = Vt + (db) * 64 * FSTR;                                    \
        _Pragma("unroll")                                                     \
        for (int i = 0; i < 4; ++i) {                                         \
            const int c0 = vhalf * 16 + i * 4;                                \
            vt[(c0 + 0) * FSTR + vtok] = vr[i].x;                             \
            vt[(c0 + 1) * FSTR + vtok] = vr[i].y;                             \
            vt[(c0 + 2) * FSTR + vtok] = vr[i].z;                             \
            vt[(c0 + 3) * FSTR + vtok] = vr[i].w;                             \
        }                                                                     \
    }

    // prologue
    FL_LOAD_K(Ks_u, Kb);
    CP_COMMIT();
    FL_LDG_V(0);

    uint32_t qf[8][4];
#pragma unroll
    for (int kb = 0; kb < 8; ++kb) {
        const int k = kb * 8 + ls;
        qf[kb][0] = __float_as_uint(Qb[(size_t)rrow * HD + k]);
        qf[kb][1] = __float_as_uint(Qb[(size_t)(rrow + 8) * HD + k]);
        qf[kb][2] = __float_as_uint(Qb[(size_t)rrow * HD + k + 4]);
        qf[kb][3] = __float_as_uint(Qb[(size_t)(rrow + 8) * HD + k + 4]);
    }

    float acc[8][4];
#pragma unroll
    for (int nt = 0; nt < 8; ++nt)
#pragma unroll
        for (int r = 0; r < 4; ++r) acc[nt][r] = 0.f;
    float m0 = -1e30f, m1 = -1e30f, l0 = 0.f, l1 = 0.f;

    const int jtmax = 2 * qi + 1;

    for (int jt = 0; jt <= jtmax; ++jt) {
        const int db = jt & 1;
        CP_WAIT(0);
        FL_STS_V(db);
        __syncthreads();

        if (jt < jtmax) {
            FL_LOAD_K(Ks_u + (uint32_t)((db ^ 1) * 64 * FSTR) * 4,
                      Kb + (size_t)(jt + 1) * 64 * HD);
            CP_COMMIT();
            FL_LDG_V(jt + 1);
        }

        // ---- S = Q K^T (ldmatrix B-frags) ----
        float sc[8][4];
#pragma unroll
        for (int nt = 0; nt < 8; ++nt)
#pragma unroll
            for (int r = 0; r < 4; ++r) sc[nt][r] = 0.f;

        const uint32_t Kd_u = Ks_u + (uint32_t)(db * 64 * FSTR) * 4;
#pragma unroll
        for (int kb = 0; kb < 8; ++kb) {
#pragma unroll
            for (int ntp = 0; ntp < 4; ++ntp) {
                uint32_t b[4];
                ldsm4(b, Kd_u + bk_lane + (uint32_t)(ntp * 16 * FSTR + kb * 8) * 4);
                mma8(sc[ntp * 2],     qf[kb], b);
                mma8(sc[ntp * 2 + 1], qf[kb], b + 2);
            }
        }

        // ---- causal mask ----
        if (jt >= 2 * qi) {
            const int rg0 = qi * 128 + rrow;
#pragma unroll
            for (int nt = 0; nt < 8; ++nt) {
                const int cg = jt * 64 + nt * 8 + ls * 2;
                if (cg > rg0)         sc[nt][0] += -1000000000.0f;
                if (cg + 1 > rg0)     sc[nt][1] += -1000000000.0f;
                if (cg > rg0 + 8)     sc[nt][2] += -1000000000.0f;
                if (cg + 1 > rg0 + 8) sc[nt][3] += -1000000000.0f;
            }
        }

        // ---- row max ----
        float mx0 = sc[0][0], mx1 = sc[0][2];
#pragma unroll
        for (int nt = 0; nt < 8; ++nt) {
            mx0 = fmaxf(mx0, fmaxf(sc[nt][0], sc[nt][1]));
            mx1 = fmaxf(mx1, fmaxf(sc[nt][2], sc[nt][3]));
        }
        mx0 = fmaxf(mx0, __shfl_xor_sync(0xffffffffu, mx0, 1));
        mx0 = fmaxf(mx0, __shfl_xor_sync(0xffffffffu, mx0, 2));
        mx1 = fmaxf(mx1, __shfl_xor_sync(0xffffffffu, mx1, 1));
        mx1 = fmaxf(mx1, __shfl_xor_sync(0xffffffffu, mx1, 2));

        const float mn0 = fmaxf(m0, mx0);
        const float mn1 = fmaxf(m1, mx1);
        const float al0 = __expf(m0 - mn0);
        const float al1 = __expf(m1 - mn1);
        m0 = mn0; m1 = mn1;

        // ---- P = exp(S - m), round, store; row sums ----
        float rs0 = 0.f, rs1 = 0.f;
#pragma unroll
        for (int nt = 0; nt < 8; ++nt) {
            const float p0 = __expf(sc[nt][0] - mn0);
            const float p1 = __expf(sc[nt][1] - mn0);
            const float p2 = __expf(sc[nt][2] - mn1);
            const float p3 = __expf(sc[nt][3] - mn1);
            rs0 += p0 + p1;  rs1 += p2 + p3;
            uint2 w0, w1;
            w0.x = f2tf(p0); w0.y = f2tf(p1);
            w1.x = f2tf(p2); w1.y = f2tf(p3);
            const int cc = nt * 8 + ls * 2;
            *(uint2*)(Ps + rrow * FSTR + cc)       = w0;
            *(uint2*)(Ps + (rrow + 8) * FSTR + cc) = w1;
        }
        rs0 += __shfl_xor_sync(0xffffffffu, rs0, 1);
        rs0 += __shfl_xor_sync(0xffffffffu, rs0, 2);
        rs1 += __shfl_xor_sync(0xffffffffu, rs1, 1);
        rs1 += __shfl_xor_sync(0xffffffffu, rs1, 2);
        l0 = l0 * al0 + rs0;
        l1 = l1 * al1 + rs1;

#pragma unroll
        for (int nt = 0; nt < 8; ++nt) {
            acc[nt][0] *= al0; acc[nt][1] *= al0;
            acc[nt][2] *= al1; acc[nt][3] *= al1;
        }
        __syncwarp();

        // ---- O += P V (ldmatrix A- and B-frags) ----
        const uint32_t Vd_u = Vt_u + (uint32_t)(db * 64 * FSTR) * 4;
#pragma unroll
        for (int kb = 0; kb < 8; ++kb) {
            uint32_t a[4];
            ldsm4(a, Ps_warp + ap_lane + (uint32_t)(kb * 8) * 4);
#pragma unroll
            for (int ntp = 0; ntp < 4; ++ntp) {
                uint32_t b[4];
                ldsm4(b, Vd_u + bk_lane + (uint32_t)(ntp * 16 * FSTR + kb * 8) * 4);
                mma8(acc[ntp * 2],     a, b);
                mma8(acc[ntp * 2 + 1], a, b + 2);
            }
        }
        __syncwarp();
    }

    // ---- epilogue ----
    const float inv0 = 1.f / l0;
    const float inv1 = 1.f / l1;
    const int b = bh >> 4;
    const int h = bh & 15;
    const int r0 = qi * 128 + rrow;
#pragma unroll
    for (int nt = 0; nt < 8; ++nt) {
        const int cn = h * HD + nt * 8 + ls * 2;
        uint2 o0, o1;
        o0.x = f2tf(acc[nt][0] * inv0); o0.y = f2tf(acc[nt][1] * inv0);
        o1.x = f2tf(acc[nt][2] * inv1); o1.y = f2tf(acc[nt][3] * inv1);
        *(uint2*)(ctx + (size_t)(b * LL + r0) * DD + cn)     = o0;
        *(uint2*)(ctx + (size_t)(b * LL + r0 + 8) * DD + cn) = o1;
    }
}

// ---------------------------------------------------------------------------
// Launch
// ---------------------------------------------------------------------------
extern "C" void kernel_launch(void* const* d_in, const int* in_sizes, int n_in,
                              void* d_out, int out_size)
{
    const float* x       = (const float*)d_in[0];
    const float* Wqkv_w  = (const float*)d_in[2];
    const float* Wqkv_b  = (const float*)d_in[3];
    const float* Wout_w  = (const float*)d_in[4];
    const float* Wout_b  = (const float*)d_in[5];

    float* out  = (float*)d_out;
    float* kout = out + BLD;
    float* vout = kout + BLD;

    float *xr, *wqkv, *wout_r, *qkv, *qh, *kh, *vh, *ctx;
    cudaGetSymbolAddress((void**)&xr,     g_xr);
    cudaGetSymbolAddress((void**)&wqkv,   g_wqkv);
    cudaGetSymbolAddress((void**)&wout_r, g_wout);
    cudaGetSymbolAddress((void**)&qkv,    g_qkv);
    cudaGetSymbolAddress((void**)&qh,     g_q);
    cudaGetSymbolAddress((void**)&kh,     g_k);
    cudaGetSymbolAddress((void**)&vh,     g_v);
    cudaGetSymbolAddress((void**)&ctx,    g_ctx);

    cudaFuncSetAttribute(gemm_mma,
                         cudaFuncAttributeMaxDynamicSharedMemorySize, GEMM_SMEM);
    cudaFuncSetAttribute(flash_mma,
                         cudaFuncAttributeMaxDynamicSharedMemorySize, FLASH_SMEM);

    round_all<<<(RND_TOTAL4 + 255) / 256, 256>>>(
        (const float4*)x, (float4*)xr,
        (const float4*)Wqkv_w, (float4*)wqkv,
        (const float4*)Wout_w, (float4*)wout_r);

    gemm_mma<<<dim3(QKV_N / 128, ROWS / 128), 256, GEMM_SMEM>>>(
        xr, wqkv, Wqkv_b, qkv, QKV_N, DD);

    rope_scatter<<<(BB * LL * HH * 32) / 256, 256>>>(qkv, qh, kh, vh, kout, vout);

    flash_mma<<<dim3(LL / 128, BB * HH), 256, FLASH_SMEM>>>(qh, kh, vh, ctx);

    gemm_mma<<<dim3(DD / 128, ROWS / 128), 256, GEMM_SMEM>>>(
        ctx, wout_r, Wout_b, out, DD, DD);
}

// round 7
// speedup vs baseline: 3.1449x; 1.0159x over previous
#include <cuda_runtime.h>
#include <cuda_bf16.h>
#include <cstdint>

// Problem shape constants (fixed by the reference).
#define BB 2
#define LL 2048
#define DD 1024
#define HH 16
#define HD 64
#define ROWS (BB*LL)            // 4096
#define QKV_N (3*DD)            // 3072
#define BLD (BB*LL*DD)          // 4194304
#define WQKV_SZ (QKV_N*DD)      // 3145728
#define WOUT_SZ (DD*DD)         // 1048576

// ---------------------------------------------------------------------------
// Scratch (alloc-free rule: __device__ globals)
// ---------------------------------------------------------------------------
__device__ float g_xr  [BLD];
__device__ float g_wqkv[WQKV_SZ];
__device__ float g_wout[WOUT_SZ];
__device__ float g_qkv [ROWS * QKV_N];
__device__ float g_q   [BLD];
__device__ float g_k   [BLD];
__device__ float g_v   [BLD];
__device__ float g_ctx [BLD];

// ---------------------------------------------------------------------------
// Helpers
// ---------------------------------------------------------------------------
__device__ __forceinline__ uint32_t f2tf(float f) {
    uint32_t r;
    asm("cvt.rna.tf32.f32 %0, %1;" : "=r"(r) : "f"(f));
    return r;
}

__device__ __forceinline__ uint32_t smem_u32(const void* p) {
    uint32_t a;
    asm("{ .reg .u64 t; cvta.to.shared.u64 t, %1; cvt.u32.u64 %0, t; }"
        : "=r"(a) : "l"(p));
    return a;
}

// m16n8k8 tf32 mma (.row.col)
__device__ __forceinline__ void mma8(float* c, const uint32_t* a, const uint32_t* b) {
    asm volatile(
        "mma.sync.aligned.m16n8k8.row.col.f32.tf32.tf32.f32 "
        "{%0,%1,%2,%3}, {%4,%5,%6,%7}, {%8,%9}, {%0,%1,%2,%3};"
        : "+f"(c[0]), "+f"(c[1]), "+f"(c[2]), "+f"(c[3])
        : "r"(a[0]), "r"(a[1]), "r"(a[2]), "r"(a[3]), "r"(b[0]), "r"(b[1]));
}

// ldmatrix x4 (b32 data viewed as b16 pairs; mapping matches mma frags)
__device__ __forceinline__ void ldsm4(uint32_t* r, uint32_t addr) {
    asm volatile(
        "ldmatrix.sync.aligned.m8n8.x4.shared.b16 {%0,%1,%2,%3}, [%4];"
        : "=r"(r[0]), "=r"(r[1]), "=r"(r[2]), "=r"(r[3]) : "r"(addr));
}

#define CP16(dst, src) \
    asm volatile("cp.async.cg.shared.global [%0], [%1], 16;" :: "r"(dst), "l"(src))
#define CP_COMMIT() asm volatile("cp.async.commit_group;" ::: "memory")
#define CP_WAIT(n)  asm volatile("cp.async.wait_group %0;" :: "n"(n) : "memory")

// ---------------------------------------------------------------------------
// Fused round-to-tf32 of x, Wqkv, Wout
// ---------------------------------------------------------------------------
#define RND_TOTAL4 ((BLD + WQKV_SZ + WOUT_SZ) / 4)

__global__ __launch_bounds__(256) void round_all(
    const float4* __restrict__ x,   float4* __restrict__ xr,
    const float4* __restrict__ wq,  float4* __restrict__ wqr,
    const float4* __restrict__ wo,  float4* __restrict__ wor)
{
    int i = blockIdx.x * 256 + threadIdx.x;
    if (i >= RND_TOTAL4) return;
    const float4* src; float4* dst;
    if (i < BLD/4)                       { src = x;  dst = xr;  }
    else if (i < (BLD + WQKV_SZ)/4)      { src = wq; dst = wqr; i -= BLD/4; }
    else                                 { src = wo; dst = wor; i -= (BLD + WQKV_SZ)/4; }
    float4 v = src[i];
    float4 o;
    o.x = __uint_as_float(f2tf(v.x));
    o.y = __uint_as_float(f2tf(v.y));
    o.z = __uint_as_float(f2tf(v.z));
    o.w = __uint_as_float(f2tf(v.w));
    dst[i] = o;
}

// ---------------------------------------------------------------------------
// tf32 mma.sync NT GEMM (unchanged from R6): 128x128 CTA tile, BK=32,
// 256 threads, ldmatrix fragments, smem stride 36.
// ---------------------------------------------------------------------------
#define GSTR 36
#define GEMM_SMEM (2 * 2 * 128 * GSTR * 4)

__global__ __launch_bounds__(256) void gemm_mma(
    const float* __restrict__ A, const float* __restrict__ B,
    const float* __restrict__ bias, float* __restrict__ C,
    int N, int K)
{
    extern __shared__ float sm[];
    float* As = sm;
    float* Bs = sm + 2 * 128 * GSTR;
    const uint32_t As_u = smem_u32(As);
    const uint32_t Bs_u = smem_u32(Bs);

    const int tid  = threadIdx.x;
    const int lane = tid & 31;
    const int wid  = tid >> 5;
    const int wm   = wid & 1;
    const int wn   = wid >> 1;
    const int lq   = lane >> 2;
    const int ls   = lane & 3;
    const int s    = lane >> 3;
    const int srow = lane & 7;

    const uint32_t a_lane =
        (uint32_t)(((wm * 64) + (s & 1) * 8 + srow) * GSTR + (s >> 1) * 4) * 4;
    const uint32_t b_lane =
        (uint32_t)(((wn * 32) + (s >> 1) * 8 + srow) * GSTR + (s & 1) * 4) * 4;

    const float* Ab = A + (size_t)(blockIdx.y * 128) * K;
    const float* Bb = B + (size_t)(blockIdx.x * 128) * K;
    const int KS = K >> 5;

    float acc[4][4][4];
#pragma unroll
    for (int mt = 0; mt < 4; ++mt)
#pragma unroll
        for (int nt = 0; nt < 4; ++nt)
#pragma unroll
            for (int r = 0; r < 4; ++r) acc[mt][nt][r] = 0.f;

#define GEMM_LOAD(ks, db)                                                     \
    {                                                                         \
        const int k0 = (ks) * 32;                                             \
        const uint32_t dA = As_u + (db) * 128 * GSTR * 4;                     \
        const uint32_t dB = Bs_u + (db) * 128 * GSTR * 4;                     \
        _Pragma("unroll")                                                     \
        for (int i = 0; i < 4; ++i) {                                         \
            const int c   = tid + i * 256;                                    \
            const int row = c >> 3;                                           \
            const int cc  = (c & 7) * 4;                                      \
            const uint32_t off = (uint32_t)(row * GSTR + cc) * 4;             \
            CP16(dA + off, Ab + (size_t)row * K + k0 + cc);                   \
            CP16(dB + off, Bb + (size_t)row * K + k0 + cc);                   \
        }                                                                     \
        CP_COMMIT();                                                          \
    }

    GEMM_LOAD(0, 0);

    for (int ks = 0; ks < KS; ++ks) {
        const int db = ks & 1;
        if (ks + 1 < KS) { GEMM_LOAD(ks + 1, db ^ 1); CP_WAIT(1); }
        else             { CP_WAIT(0); }
        __syncthreads();

        const uint32_t Ad_u = As_u + db * 128 * GSTR * 4;
        const uint32_t Bd_u = Bs_u + db * 128 * GSTR * 4;

#pragma unroll
        for (int kb = 0; kb < 4; ++kb) {
            uint32_t a[4][4], b[2][4];
#pragma unroll
            for (int mt = 0; mt < 4; ++mt)
                ldsm4(a[mt], Ad_u + a_lane + (uint32_t)(mt * 16 * GSTR + kb * 8) * 4);
#pragma unroll
            for (int ntp = 0; ntp < 2; ++ntp)
                ldsm4(b[ntp], Bd_u + b_lane + (uint32_t)(ntp * 16 * GSTR + kb * 8) * 4);
#pragma unroll
            for (int mt = 0; mt < 4; ++mt)
#pragma unroll
                for (int nt = 0; nt < 4; ++nt)
                    mma8(acc[mt][nt], a[mt], &b[nt >> 1][(nt & 1) * 2]);
        }
        __syncthreads();
    }

    const int row_base = blockIdx.y * 128 + wm * 64;
    const int col_base = blockIdx.x * 128 + wn * 32;
#pragma unroll
    for (int mt = 0; mt < 4; ++mt) {
        const int r0 = row_base + mt * 16 + lq;
#pragma unroll
        for (int nt = 0; nt < 4; ++nt) {
            const int cn = col_base + nt * 8 + ls * 2;
            const float2 bb = *(const float2*)(bias + cn);
            float2 o0, o1;
            o0.x = acc[mt][nt][0] + bb.x;  o0.y = acc[mt][nt][1] + bb.y;
            o1.x = acc[mt][nt][2] + bb.x;  o1.y = acc[mt][nt][3] + bb.y;
            *(float2*)(C + (size_t)r0 * N + cn)       = o0;
            *(float2*)(C + (size_t)(r0 + 8) * N + cn) = o1;
        }
    }
}

// ---------------------------------------------------------------------------
// RoPE + head scatter (unchanged).
// ---------------------------------------------------------------------------
__global__ __launch_bounds__(256) void rope_scatter(
    const float* __restrict__ qkv,
    float* __restrict__ qh, float* __restrict__ kh, float* __restrict__ vh,
    float* __restrict__ kout, float* __restrict__ vout)
{
    const int t = blockIdx.x * blockDim.x + threadIdx.x;
    const int d = t & 31;
    const int h = (t >> 5) & 15;
    const int l = (t >> 9) & 2047;
    const int b = t >> 20;

    const float* base = qkv + (size_t)(b * LL + l) * QKV_N;

    const float inv = __expf(-(float)d * (9.210340371976184f / 32.f));
    const float ang = (float)l * inv;
    float sn, cs;
    sincosf(ang, &sn, &cs);

    const size_t ob = ((size_t)((b * HH + h) * LL + l)) * HD;

    const float q1 = base[h*HD + d], q2 = base[h*HD + d + 32];
    qh[ob + d]      = __uint_as_float(f2tf((q1 * cs - q2 * sn) * 0.125f));
    qh[ob + d + 32] = __uint_as_float(f2tf((q1 * sn + q2 * cs) * 0.125f));

    const float k1 = base[DD + h*HD + d], k2 = base[DD + h*HD + d + 32];
    const float kr1 = k1 * cs - k2 * sn;
    const float kr2 = k1 * sn + k2 * cs;
    kout[ob + d]      = kr1;
    kout[ob + d + 32] = kr2;
    kh[ob + d]        = __uint_as_float(f2tf(kr1));
    kh[ob + d + 32]   = __uint_as_float(f2tf(kr2));

    const float v1 = base[2*DD + h*HD + d], v2 = base[2*DD + h*HD + d + 32];
    vout[ob + d]      = v1;
    vout[ob + d + 32] = v2;
    vh[ob + d]        = __uint_as_float(f2tf(v1));
    vh[ob + d + 32]   = __uint_as_float(f2tf(v2));
}

// ---------------------------------------------------------------------------
// Flash attention v4: Br=128, Bc=64, 512 threads (16 warps).
// Warp (wr=wid&7, wc=wid>>3): rows wr*16..+16, K-columns wc*32..+32.
// Column-split online softmax: per-warp independent (m,l,acc); split-KV
// combine in the epilogue. P is warp-private smem (16 x PSTR slice).
// smem: Ks[2][64*FSTR] | Vt[2][64*FSTR] | Ps[16][16*PSTR] | cm[256] | cl[256]
// Epilogue 'ac' buffer (128 x 66) aliases the Ks region (dead by then).
// ---------------------------------------------------------------------------
#define FSTR 68
#define PSTR 36
#define VT_OFFF (2*64*FSTR)
#define PS_OFFF (VT_OFFF + 2*64*FSTR)
#define CM_OFFF (PS_OFFF + 16*16*PSTR)
#define CL_OFFF (CM_OFFF + 256)
#define FLASH_SMEM ((CL_OFFF + 256) * 4)

__global__ __launch_bounds__(512) void flash_mma(
    const float* __restrict__ Q, const float* __restrict__ K,
    const float* __restrict__ V, float* __restrict__ ctx)
{
    extern __shared__ float sm[];
    float* Ks = sm;
    float* Vt = sm + VT_OFFF;
    float* Ps = sm + PS_OFFF;
    float* cm = sm + CM_OFFF;
    float* cl = sm + CL_OFFF;
    float* ac = sm;                      // epilogue alias of Ks, stride 66
    const uint32_t Ks_u = smem_u32(Ks);
    const uint32_t Vt_u = smem_u32(Vt);
    const uint32_t Ps_u = smem_u32(Ps);

    const int qi   = gridDim.x - 1 - blockIdx.x;   // heavy tiles first
    const int bh   = blockIdx.y;
    const int tid  = threadIdx.x;
    const int lane = tid & 31;
    const int wid  = tid >> 5;           // 0..15
    const int wr   = wid & 7;            // row group
    const int wc   = wid >> 3;           // col group (0,1)
    const int lq   = lane >> 2;
    const int ls   = lane & 3;
    const int s    = lane >> 3;
    const int srow = lane & 7;
    const int rrow = wr * 16 + lq;       // rows rrow, rrow+8 (0..127)

    // ldmatrix lane offsets (bytes)
    const uint32_t bk_lane =
        (uint32_t)(((s >> 1) * 8 + srow) * FSTR + (s & 1) * 4) * 4;
    const uint32_t ap_lane =
        (uint32_t)(((s & 1) * 8 + srow) * PSTR + (s >> 1) * 4) * 4;
    const uint32_t Psw_u = Ps_u + (uint32_t)(wid * 16 * PSTR) * 4;
    float* Psw = Ps + wid * 16 * PSTR;

    const float* Qb = Q + ((size_t)bh * LL + qi * 128) * HD;
    const float* Kb = K + (size_t)bh * LL * HD;
    const float* Vb = V + (size_t)bh * LL * HD;

#define FL_LOAD_K(dst_u, src)                                                 \
    {                                                                         \
        _Pragma("unroll")                                                     \
        for (int i = 0; i < 2; ++i) {                                         \
            const int c   = tid + i * 512;                                    \
            const int row = c >> 4;                                           \
            const int cc  = (c & 15) * 4;                                     \
            CP16((dst_u) + (uint32_t)(row * FSTR + cc) * 4,                   \
                 (src) + (size_t)row * HD + cc);                              \
        }                                                                     \
    }

    const int vtok = tid & 63;
    const int vseg = tid >> 6;           // 0..7 -> 8 dims each

    float4 vr[2];
#define FL_LDG_V(jt)                                                          \
    {                                                                         \
        const float* vb = Vb + ((size_t)(jt) * 64 + vtok) * HD + vseg * 8;    \
        vr[0] = *(const float4*)(vb);                                         \
        vr[1] = *(const float4*)(vb + 4);                                     \
    }

#define FL_STS_V(db)                                                          \
    {                                                                         \
        float* vt = Vt + (db) * 64 * FSTR;                                    \
        _Pragma("unroll")                                                     \
        for (int i = 0; i < 2; ++i) {                                         \
            const int c0 = vseg * 8 + i * 4;                                  \
            vt[(c0 + 0) * FSTR + vtok] = vr[i].x;                             \
            vt[(c0 + 1) * FSTR + vtok] = vr[i].y;                             \
            vt[(c0 + 2) * FSTR + vtok] = vr[i].z;                             \
            vt[(c0 + 3) * FSTR + vtok] = vr[i].w;                             \
        }                                                                     \
    }

    // prologue
    FL_LOAD_K(Ks_u, Kb);
    CP_COMMIT();
    FL_LDG_V(0);

    uint32_t qf[8][4];
#pragma unroll
    for (int kb = 0; kb < 8; ++kb) {
        const int k = kb * 8 + ls;
        qf[kb][0] = __float_as_uint(Qb[(size_t)rrow * HD + k]);
        qf[kb][1] = __float_as_uint(Qb[(size_t)(rrow + 8) * HD + k]);
        qf[kb][2] = __float_as_uint(Qb[(size_t)rrow * HD + k + 4]);
        qf[kb][3] = __float_as_uint(Qb[(size_t)(rrow + 8) * HD + k + 4]);
    }

    float acc[8][4];
#pragma unroll
    for (int nt = 0; nt < 8; ++nt)
#pragma unroll
        for (int r = 0; r < 4; ++r) acc[nt][r] = 0.f;
    float m0 = -1e30f, m1 = -1e30f, l0 = 0.f, l1 = 0.f;

    const int jtmax = 2 * qi + 1;

    for (int jt = 0; jt <= jtmax; ++jt) {
        const int db = jt & 1;
        CP_WAIT(0);
        FL_STS_V(db);
        __syncthreads();

        if (jt < jtmax) {
            FL_LOAD_K(Ks_u + (uint32_t)((db ^ 1) * 64 * FSTR) * 4,
                      Kb + (size_t)(jt + 1) * 64 * HD);
            CP_COMMIT();
            FL_LDG_V(jt + 1);
        }

        // ---- S = Q K^T on this warp's 32 K-columns ----
        float sc[4][4];
#pragma unroll
        for (int nt = 0; nt < 4; ++nt)
#pragma unroll
            for (int r = 0; r < 4; ++r) sc[nt][r] = 0.f;

        const uint32_t Kd_u = Ks_u + (uint32_t)(db * 64 * FSTR) * 4
                            + (uint32_t)(wc * 32 * FSTR) * 4 + bk_lane;
#pragma unroll
        for (int kb = 0; kb < 8; ++kb) {
#pragma unroll
            for (int ntp = 0; ntp < 2; ++ntp) {
                uint32_t b[4];
                ldsm4(b, Kd_u + (uint32_t)(ntp * 16 * FSTR + kb * 8) * 4);
                mma8(sc[ntp * 2],     qf[kb], b);
                mma8(sc[ntp * 2 + 1], qf[kb], b + 2);
            }
        }

        // ---- causal mask ----
        if (jt >= 2 * qi) {
            const int rg0 = qi * 128 + rrow;
            const int cbase = jt * 64 + wc * 32;
#pragma unroll
            for (int nt = 0; nt < 4; ++nt) {
                const int cg = cbase + nt * 8 + ls * 2;
                if (cg > rg0)         sc[nt][0] += -1000000000.0f;
                if (cg + 1 > rg0)     sc[nt][1] += -1000000000.0f;
                if (cg > rg0 + 8)     sc[nt][2] += -1000000000.0f;
                if (cg + 1 > rg0 + 8) sc[nt][3] += -1000000000.0f;
            }
        }

        // ---- row max over this warp's 32 cols (quad shfl) ----
        float mx0 = sc[0][0], mx1 = sc[0][2];
#pragma unroll
        for (int nt = 0; nt < 4; ++nt) {
            mx0 = fmaxf(mx0, fmaxf(sc[nt][0], sc[nt][1]));
            mx1 = fmaxf(mx1, fmaxf(sc[nt][2], sc[nt][3]));
        }
        mx0 = fmaxf(mx0, __shfl_xor_sync(0xffffffffu, mx0, 1));
        mx0 = fmaxf(mx0, __shfl_xor_sync(0xffffffffu, mx0, 2));
        mx1 = fmaxf(mx1, __shfl_xor_sync(0xffffffffu, mx1, 1));
        mx1 = fmaxf(mx1, __shfl_xor_sync(0xffffffffu, mx1, 2));

        const float mn0 = fmaxf(m0, mx0);
        const float mn1 = fmaxf(m1, mx1);
        const float al0 = __expf(m0 - mn0);
        const float al1 = __expf(m1 - mn1);
        m0 = mn0; m1 = mn1;

        // ---- P = exp(S - m), round, store to own Ps slice; row sums ----
        float rs0 = 0.f, rs1 = 0.f;
#pragma unroll
        for (int nt = 0; nt < 4; ++nt) {
            const float p0 = __expf(sc[nt][0] - mn0);
            const float p1 = __expf(sc[nt][1] - mn0);
            const float p2 = __expf(sc[nt][2] - mn1);
            const float p3 = __expf(sc[nt][3] - mn1);
            rs0 += p0 + p1;  rs1 += p2 + p3;
            uint2 w0, w1;
            w0.x = f2tf(p0); w0.y = f2tf(p1);
            w1.x = f2tf(p2); w1.y = f2tf(p3);
            const int cc = nt * 8 + ls * 2;
            *(uint2*)(Psw + lq * PSTR + cc)       = w0;
            *(uint2*)(Psw + (lq + 8) * PSTR + cc) = w1;
        }
        rs0 += __shfl_xor_sync(0xffffffffu, rs0, 1);
        rs0 += __shfl_xor_sync(0xffffffffu, rs0, 2);
        rs1 += __shfl_xor_sync(0xffffffffu, rs1, 1);
        rs1 += __shfl_xor_sync(0xffffffffu, rs1, 2);
        l0 = l0 * al0 + rs0;
        l1 = l1 * al1 + rs1;

#pragma unroll
        for (int nt = 0; nt < 8; ++nt) {
            acc[nt][0] *= al0; acc[nt][1] *= al0;
            acc[nt][2] *= al1; acc[nt][3] *= al1;
        }
        __syncwarp();                    // Ps slice visible to own ldmatrix

        // ---- O += P V over this warp's 32 tokens, full 64 head dims ----
        const uint32_t Vd_u = Vt_u + (uint32_t)(db * 64 * FSTR) * 4 + bk_lane;
#pragma unroll
        for (int kb = 0; kb < 4; ++kb) {
            uint32_t a[4];
            ldsm4(a, Psw_u + ap_lane + (uint32_t)(kb * 8) * 4);
#pragma unroll
            for (int ntp = 0; ntp < 4; ++ntp) {
                uint32_t b[4];
                ldsm4(b, Vd_u +
                      (uint32_t)(ntp * 16 * FSTR + wc * 32 + kb * 8) * 4);
                mma8(acc[ntp * 2],     a, b);
                mma8(acc[ntp * 2 + 1], a, b + 2);
            }
        }
        __syncwarp();
    }

    // ---- epilogue: split-KV combine of the two column-warps ----
    if (ls == 0) {
        cm[wc * 128 + rrow]     = m0;  cm[wc * 128 + rrow + 8] = m1;
        cl[wc * 128 + rrow]     = l0;  cl[wc * 128 + rrow + 8] = l1;
    }
    __syncthreads();                     // also fences all loop smem reads

    const float mo0 = cm[(wc ^ 1) * 128 + rrow];
    const float mo1 = cm[(wc ^ 1) * 128 + rrow + 8];
    const float lo0 = cl[(wc ^ 1) * 128 + rrow];
    const float lo1 = cl[(wc ^ 1) * 128 + rrow + 8];
    const float M0 = fmaxf(m0, mo0), M1 = fmaxf(m1, mo1);
    const float s0 = __expf(m0 - M0),  s1 = __expf(m1 - M1);
    const float so0 = __expf(mo0 - M0), so1 = __expf(mo1 - M1);
    const float lt0 = l0 * s0 + lo0 * so0;
    const float lt1 = l1 * s1 + lo1 * so1;

    if (wc == 1) {                       // publish scaled partial O
#pragma unroll
        for (int nt = 0; nt < 8; ++nt) {
            const int cc = nt * 8 + ls * 2;
            float2 w0, w1;
            w0.x = acc[nt][0] * s0; w0.y = acc[nt][1] * s0;
            w1.x = acc[nt][2] * s1; w1.y = acc[nt][3] * s1;
            *(float2*)(ac + rrow * 66 + cc)       = w0;
            *(float2*)(ac + (rrow + 8) * 66 + cc) = w1;
        }
    }
    __syncthreads();

    if (wc == 0) {
        const float inv0 = 1.f / lt0;
        const float inv1 = 1.f / lt1;
        const int b = bh >> 4;
        const int h = bh & 15;
        const int r0 = qi * 128 + rrow;
#pragma unroll
        for (int nt = 0; nt < 8; ++nt) {
            const int cc = nt * 8 + ls * 2;
            const float2 p0 = *(const float2*)(ac + rrow * 66 + cc);
            const float2 p1 = *(const float2*)(ac + (rrow + 8) * 66 + cc);
            const int cn = h * HD + cc;
            uint2 o0, o1;
            o0.x = f2tf((acc[nt][0] * s0 + p0.x) * inv0);
            o0.y = f2tf((acc[nt][1] * s0 + p0.y) * inv0);
            o1.x = f2tf((acc[nt][2] * s1 + p1.x) * inv1);
            o1.y = f2tf((acc[nt][3] * s1 + p1.y) * inv1);
            *(uint2*)(ctx + (size_t)(b * LL + r0) * DD + cn)     = o0;
            *(uint2*)(ctx + (size_t)(b * LL + r0 + 8) * DD + cn) = o1;
        }
    }
}

// ---------------------------------------------------------------------------
// Launch
// ---------------------------------------------------------------------------
extern "C" void kernel_launch(void* const* d_in, const int* in_sizes, int n_in,
                              void* d_out, int out_size)
{
    const float* x       = (const float*)d_in[0];
    const float* Wqkv_w  = (const float*)d_in[2];
    const float* Wqkv_b  = (const float*)d_in[3];
    const float* Wout_w  = (const float*)d_in[4];
    const float* Wout_b  = (const float*)d_in[5];

    float* out  = (float*)d_out;
    float* kout = out + BLD;
    float* vout = kout + BLD;

    float *xr, *wqkv, *wout_r, *qkv, *qh, *kh, *vh, *ctx;
    cudaGetSymbolAddress((void**)&xr,     g_xr);
    cudaGetSymbolAddress((void**)&wqkv,   g_wqkv);
    cudaGetSymbolAddress((void**)&wout_r, g_wout);
    cudaGetSymbolAddress((void**)&qkv,    g_qkv);
    cudaGetSymbolAddress((void**)&qh,     g_q);
    cudaGetSymbolAddress((void**)&kh,     g_k);
    cudaGetSymbolAddress((void**)&vh,     g_v);
    cudaGetSymbolAddress((void**)&ctx,    g_ctx);

    cudaFuncSetAttribute(gemm_mma,
                         cudaFuncAttributeMaxDynamicSharedMemorySize, GEMM_SMEM);
    cudaFuncSetAttribute(flash_mma,
                         cudaFuncAttributeMaxDynamicSharedMemorySize, FLASH_SMEM);

    round_all<<<(RND_TOTAL4 + 255) / 256, 256>>>(
        (const float4*)x, (float4*)xr,
        (const float4*)Wqkv_w, (float4*)wqkv,
        (const float4*)Wout_w, (float4*)wout_r);

    gemm_mma<<<dim3(QKV_N / 128, ROWS / 128), 256, GEMM_SMEM>>>(
        xr, wqkv, Wqkv_b, qkv, QKV_N, DD);

    rope_scatter<<<(BB * LL * HH * 32) / 256, 256>>>(qkv, qh, kh, vh, kout, vout);

    flash_mma<<<dim3(LL / 128, BB * HH), 512, FLASH_SMEM>>>(qh, kh, vh, ctx);

    gemm_mma<<<dim3(DD / 128, ROWS / 128), 256, GEMM_SMEM>>>(
        ctx, wout_r, Wout_b, out, DD, DD);
}